// round 1
// baseline (speedup 1.0000x reference)
#include <cuda_runtime.h>
#include <cuda_bf16.h>
#include <math.h>

// ---------------- problem constants ----------------
#define NB     4
#define L_SP   5440
#define N_VT   8
#define LQ     (L_SP + N_VT)      // 5448
#define DM     256
#define DF     1024
#define NH     8
#define DH     32
#define NLEV   4
#define NPTS   4
#define ROWS   (NB * LQ)          // 21792
#define EPSLN  1e-5f

__device__ __constant__ int c_H[NLEV]     = {64, 32, 16, 8};
__device__ __constant__ int c_W[NLEV]     = {64, 32, 16, 8};
__device__ __constant__ int c_start[NLEV] = {0, 4096, 5120, 5376};

// ---------------- scratch (device globals; no allocs allowed) ----------------
static __device__ float g_q   [ (size_t)ROWS * DM ];   // query = src+pos / sel_vt ; later reused as proj/h buffer
static __device__ float g_v   [ (size_t)ROWS * DM ];   // v_in
static __device__ float g_val [ (size_t)ROWS * DM ];   // value = v_in @ Wv^T + bv
static __device__ float g_off [ (size_t)ROWS * DM ];   // sampling offsets (256 per row)
static __device__ float g_attn[ (size_t)ROWS * 128 ];  // attn logits -> softmaxed
static __device__ float g_samp[ (size_t)ROWS * DM ];   // deformable attn output ; later reused
static __device__ float g_x   [ (size_t)ROWS * DM ];   // post-LN1 / final x
static __device__ float g_h1  [ (size_t)ROWS * DF ];   // FFN hidden

// ---------------- build q and v_in ----------------
__global__ void build_qv_kernel(const float* __restrict__ src,
                                const float* __restrict__ pos,
                                const float* __restrict__ sel_vt)
{
    size_t idx = (size_t)blockIdx.x * blockDim.x + threadIdx.x;
    size_t total = (size_t)ROWS * DM;
    if (idx >= total) return;
    size_t row = idx / DM;
    int d = (int)(idx % DM);
    int n = (int)(row / LQ);
    int r = (int)(row % LQ);
    float qv, vv;
    if (r < L_SP) {
        size_t si = ((size_t)n * L_SP + r) * DM + d;
        float s = src[si];
        qv = s + pos[si];
        vv = s;
    } else {
        size_t si = ((size_t)n * N_VT + (r - L_SP)) * DM + d;
        float s = sel_vt[si];
        qv = s; vv = s;
    }
    g_q[idx] = qv;
    g_v[idx] = vv;
}

// ---------------- tiled fp32 GEMM: C[M,N] = A[M,K] @ B[N,K]^T + bias, optional relu ----------------
// BM=BN=64, BK=16, 256 threads, 4x4 microtile
__global__ void gemm_bias_kernel(const float* __restrict__ A,
                                 const float* __restrict__ B,
                                 const float* __restrict__ bias,
                                 float* __restrict__ C,
                                 int M, int N, int K, int relu)
{
    __shared__ float As[16][64 + 1];
    __shared__ float Bs[16][64 + 1];
    const int bm = blockIdx.y * 64;
    const int bn = blockIdx.x * 64;
    const int tx = threadIdx.x & 15;
    const int ty = threadIdx.x >> 4;

    float acc[4][4];
#pragma unroll
    for (int i = 0; i < 4; i++)
#pragma unroll
        for (int j = 0; j < 4; j++) acc[i][j] = 0.f;

    for (int k0 = 0; k0 < K; k0 += 16) {
        // load A tile (64 rows x 16 k)
#pragma unroll
        for (int t = 0; t < 4; t++) {
            int i = threadIdx.x + t * 256;
            int m = i >> 4, k = i & 15;
            int gm = bm + m;
            As[k][m] = (gm < M) ? A[(size_t)gm * K + k0 + k] : 0.f;
        }
#pragma unroll
        for (int t = 0; t < 4; t++) {
            int i = threadIdx.x + t * 256;
            int nn = i >> 4, k = i & 15;
            int gn = bn + nn;
            Bs[k][nn] = (gn < N) ? B[(size_t)gn * K + k0 + k] : 0.f;
        }
        __syncthreads();
#pragma unroll
        for (int k = 0; k < 16; k++) {
            float a[4], b[4];
#pragma unroll
            for (int i = 0; i < 4; i++) a[i] = As[k][ty * 4 + i];
#pragma unroll
            for (int j = 0; j < 4; j++) b[j] = Bs[k][tx * 4 + j];
#pragma unroll
            for (int i = 0; i < 4; i++)
#pragma unroll
                for (int j = 0; j < 4; j++) acc[i][j] = fmaf(a[i], b[j], acc[i][j]);
        }
        __syncthreads();
    }

#pragma unroll
    for (int i = 0; i < 4; i++) {
        int m = bm + ty * 4 + i;
        if (m >= M) continue;
#pragma unroll
        for (int j = 0; j < 4; j++) {
            int n = bn + tx * 4 + j;
            if (n >= N) continue;
            float v = acc[i][j] + (bias ? bias[n] : 0.f);
            if (relu) v = fmaxf(v, 0.f);
            C[(size_t)m * N + n] = v;
        }
    }
}

// ---------------- softmax over 16 points per (row, head) ----------------
__global__ void softmax16_kernel()
{
    int t = blockIdx.x * blockDim.x + threadIdx.x;
    if (t >= ROWS * NH) return;
    size_t base = (size_t)(t >> 3) * 128 + (t & 7) * 16;
    float v[16];
    float mx = -1e30f;
#pragma unroll
    for (int i = 0; i < 16; i++) { v[i] = g_attn[base + i]; mx = fmaxf(mx, v[i]); }
    float s = 0.f;
#pragma unroll
    for (int i = 0; i < 16; i++) { v[i] = __expf(v[i] - mx); s += v[i]; }
    float inv = 1.f / s;
#pragma unroll
    for (int i = 0; i < 16; i++) g_attn[base + i] = v[i] * inv;
}

// ---------------- deformable sampling: block = (n,q), warp = head, lane = dim ----------------
__global__ void sample_kernel(const float* __restrict__ ref)
{
    const int row = blockIdx.x;            // 0..ROWS-1
    const int m   = threadIdx.x >> 5;      // head
    const int d   = threadIdx.x & 31;      // dim within head
    const int n   = row / LQ;

    const float* refp = ref + (size_t)row * (NLEV * 2);
    const float* offp = g_off + (size_t)row * DM + m * (NLEV * NPTS * 2);
    const float* attp = g_attn + (size_t)row * 128 + m * 16;
    const float* valn = g_val + (size_t)n * LQ * DM;   // value rows for batch n

    float acc = 0.f;
#pragma unroll
    for (int l = 0; l < NLEV; l++) {
        const int H = c_H[l], W = c_W[l], st = c_start[l];
        const float rx = refp[l * 2 + 0];
        const float ry = refp[l * 2 + 1];
#pragma unroll
        for (int p = 0; p < NPTS; p++) {
            const float ox = offp[(l * NPTS + p) * 2 + 0];
            const float oy = offp[(l * NPTS + p) * 2 + 1];
            const float a  = attp[l * NPTS + p];
            const float x = rx * W + ox - 0.5f;
            const float y = ry * H + oy - 0.5f;
            const float x0f = floorf(x), y0f = floorf(y);
            const float wx = x - x0f, wy = y - y0f;
            const int x0 = (int)x0f, y0 = (int)y0f;
            const int x1 = x0 + 1,   y1 = y0 + 1;
            const bool vx0 = (x0 >= 0) & (x0 < W);
            const bool vx1 = (x1 >= 0) & (x1 < W);
            const bool vy0 = (y0 >= 0) & (y0 < H);
            const bool vy1 = (y1 >= 0) & (y1 < H);
            const float w00 = (1.f - wx) * (1.f - wy);
            const float w10 = wx * (1.f - wy);
            const float w01 = (1.f - wx) * wy;
            const float w11 = wx * wy;
            if (vx0 & vy0) acc += a * w00 * valn[((size_t)(st + y0 * W + x0)) * DM + m * DH + d];
            if (vx1 & vy0) acc += a * w10 * valn[((size_t)(st + y0 * W + x1)) * DM + m * DH + d];
            if (vx0 & vy1) acc += a * w01 * valn[((size_t)(st + y1 * W + x0)) * DM + m * DH + d];
            if (vx1 & vy1) acc += a * w11 * valn[((size_t)(st + y1 * W + x1)) * DM + m * DH + d];
        }
    }
    g_samp[(size_t)row * DM + m * DH + d] = acc;
}

// ---------------- residual + LayerNorm: out = LN(a + b) ----------------
__global__ void resid_ln_kernel(const float* __restrict__ a,
                                const float* __restrict__ b,
                                const float* __restrict__ g,
                                const float* __restrict__ beta,
                                float* __restrict__ out)
{
    __shared__ float red[64];
    const int row = blockIdx.x;
    const int t = threadIdx.x;
    size_t base = (size_t)row * DM;
    float x = a[base + t] + b[base + t];

    // reduce sum
    float s = x;
#pragma unroll
    for (int o = 16; o > 0; o >>= 1) s += __shfl_xor_sync(0xffffffffu, s, o);
    if ((t & 31) == 0) red[t >> 5] = s;
    __syncthreads();
    if (t < 8) {
        float v = red[t];
#pragma unroll
        for (int o = 4; o > 0; o >>= 1) v += __shfl_xor_sync(0xffu, v, o);
        if (t == 0) red[32] = v;
    }
    __syncthreads();
    float mean = red[32] * (1.f / DM);

    float xc = x - mean;
    float sq = xc * xc;
#pragma unroll
    for (int o = 16; o > 0; o >>= 1) sq += __shfl_xor_sync(0xffffffffu, sq, o);
    if ((t & 31) == 0) red[t >> 5] = sq;
    __syncthreads();
    if (t < 8) {
        float v = red[t];
#pragma unroll
        for (int o = 4; o > 0; o >>= 1) v += __shfl_xor_sync(0xffu, v, o);
        if (t == 0) red[33] = v;
    }
    __syncthreads();
    float var = red[33] * (1.f / DM);
    float inv = rsqrtf(var + EPSLN);
    out[base + t] = g[t] * xc * inv + beta[t];
}

// ---------------- assemble final output ----------------
__global__ void write_out_kernel(const float* __restrict__ all_vt, float* __restrict__ out)
{
    const size_t P1 = (size_t)NB * L_SP * DM;          // x spatial part
    const size_t P2 = (size_t)NB * 75 * N_VT * DM;     // all_vt passthrough
    const size_t P3 = (size_t)NB * N_VT * DM;          // x vt part
    size_t idx = (size_t)blockIdx.x * blockDim.x + threadIdx.x;
    if (idx < P1) {
        size_t row = idx / DM; int d = (int)(idx % DM);
        int n = (int)(row / L_SP), r = (int)(row % L_SP);
        out[idx] = g_x[((size_t)n * LQ + r) * DM + d];
    } else if (idx < P1 + P2) {
        out[idx] = all_vt[idx - P1];
    } else if (idx < P1 + P2 + P3) {
        size_t k = idx - P1 - P2;
        size_t row = k / DM; int d = (int)(k % DM);
        int n = (int)(row / N_VT), r = (int)(row % N_VT);
        out[idx] = g_x[((size_t)n * LQ + L_SP + r) * DM + d];
    }
}

// ---------------- launch ----------------
extern "C" void kernel_launch(void* const* d_in, const int* in_sizes, int n_in,
                              void* d_out, int out_size)
{
    const float* src     = (const float*)d_in[0];
    const float* pos     = (const float*)d_in[1];
    const float* refpts  = (const float*)d_in[2];
    // d_in[3] spatial_shapes (int32), d_in[4] level_start_index, d_in[5] padding_mask (all false) -> unused
    const float* all_vt  = (const float*)d_in[6];
    const float* sel_vt  = (const float*)d_in[7];
    const float* W_value = (const float*)d_in[8];
    const float* b_value = (const float*)d_in[9];
    const float* W_off   = (const float*)d_in[10];
    const float* b_off   = (const float*)d_in[11];
    const float* W_attn  = (const float*)d_in[12];
    const float* b_attn  = (const float*)d_in[13];
    const float* W_out   = (const float*)d_in[14];
    const float* b_out   = (const float*)d_in[15];
    const float* g1      = (const float*)d_in[16];
    const float* beta1   = (const float*)d_in[17];
    const float* W1      = (const float*)d_in[18];
    const float* bf1     = (const float*)d_in[19];
    const float* W2      = (const float*)d_in[20];
    const float* bf2     = (const float*)d_in[21];
    const float* g2      = (const float*)d_in[22];
    const float* beta2   = (const float*)d_in[23];
    float* out = (float*)d_out;

    float* p_q;    cudaGetSymbolAddress((void**)&p_q,    g_q);
    float* p_v;    cudaGetSymbolAddress((void**)&p_v,    g_v);
    float* p_val;  cudaGetSymbolAddress((void**)&p_val,  g_val);
    float* p_off;  cudaGetSymbolAddress((void**)&p_off,  g_off);
    float* p_attn; cudaGetSymbolAddress((void**)&p_attn, g_attn);
    float* p_samp; cudaGetSymbolAddress((void**)&p_samp, g_samp);
    float* p_x;    cudaGetSymbolAddress((void**)&p_x,    g_x);
    float* p_h1;   cudaGetSymbolAddress((void**)&p_h1,   g_h1);

    const int M = ROWS;

    // 1. build q, v_in
    {
        size_t total = (size_t)ROWS * DM;
        build_qv_kernel<<<(unsigned)((total + 255) / 256), 256>>>(src, pos, sel_vt);
    }

    dim3 gB(4, (M + 63) / 64);   // N=256
    // 2. value = v_in @ Wv^T + bv
    gemm_bias_kernel<<<gB, 256>>>(p_v, W_value, b_value, p_val, M, DM, DM, 0);
    // 3. off = q @ Wo^T + bo
    gemm_bias_kernel<<<gB, 256>>>(p_q, W_off, b_off, p_off, M, DM, DM, 0);
    // 4. attn logits = q @ Wa^T + ba  (N=128)
    {
        dim3 gA(2, (M + 63) / 64);
        gemm_bias_kernel<<<gA, 256>>>(p_q, W_attn, b_attn, p_attn, M, 128, DM, 0);
    }
    // 5. softmax over 16 points per (row, head)
    softmax16_kernel<<<(ROWS * NH + 255) / 256, 256>>>();
    // 6. deformable sampling
    sample_kernel<<<ROWS, 256>>>(refpts);
    // 7. src2 = samp @ W_out^T + b_out  -> g_q (reuse)
    gemm_bias_kernel<<<gB, 256>>>(p_samp, W_out, b_out, p_q, M, DM, DM, 0);
    // 8. x = LN(v_in + src2)
    resid_ln_kernel<<<ROWS, 256>>>(p_v, p_q, g1, beta1, p_x);
    // 9. h1 = relu(x @ W1^T + bf1)   N=1024
    {
        dim3 gF(16, (M + 63) / 64);
        gemm_bias_kernel<<<gF, 256>>>(p_x, W1, bf1, p_h1, M, DF, DM, 1);
    }
    // 10. h = h1 @ W2^T + bf2   K=1024 -> g_q (reuse)
    gemm_bias_kernel<<<gB, 256>>>(p_h1, W2, bf2, p_q, M, DM, DF, 0);
    // 11. x = LN(x + h)  (in-place on g_x)
    resid_ln_kernel<<<ROWS, 256>>>(p_x, p_q, g2, beta2, p_x);
    // 12. assemble outputs
    {
        size_t total = (size_t)NB * (L_SP + 75 * N_VT + N_VT) * DM;
        write_out_kernel<<<(unsigned)((total + 255) / 256), 256>>>(all_vt, out);
    }
}

// round 4
// speedup vs baseline: 2.2817x; 2.2817x over previous
#include <cuda_runtime.h>
#include <cuda_bf16.h>
#include <math.h>
#include <cstdint>

// ---------------- problem constants ----------------
#define NB     4
#define L_SP   5440
#define N_VT   8
#define LQ     (L_SP + N_VT)      // 5448
#define DM     256
#define DF     1024
#define NH     8
#define DH     32
#define NLEV   4
#define NPTS   4
#define ROWS   (NB * LQ)          // 21792
#define EPSLN  1e-5f

__device__ __constant__ int c_H[NLEV]     = {64, 32, 16, 8};
__device__ __constant__ int c_W[NLEV]     = {64, 32, 16, 8};
__device__ __constant__ int c_start[NLEV] = {0, 4096, 5120, 5376};

// ---------------- scratch (device globals; no allocs) ----------------
static __device__ float g_v   [ (size_t)ROWS * DM ];   // v_in fp32 (residual 1)
static __device__ float g_val [ (size_t)ROWS * DM ];   // value projection fp32
static __device__ float g_off [ (size_t)ROWS * DM ];   // sampling offsets fp32
static __device__ float g_attn[ (size_t)ROWS * 128 ];  // attn logits -> softmax
static __device__ float g_tmp [ (size_t)ROWS * DM ];   // src2 / ffn2 out
static __device__ float g_x   [ (size_t)ROWS * DM ];   // post-LN1 / final x

// bf16 split operand buffers
static __device__ __nv_bfloat16 g_qh [ (size_t)ROWS * DM ];
static __device__ __nv_bfloat16 g_ql [ (size_t)ROWS * DM ];
static __device__ __nv_bfloat16 g_vh [ (size_t)ROWS * DM ];
static __device__ __nv_bfloat16 g_vl [ (size_t)ROWS * DM ];
static __device__ __nv_bfloat16 g_sh [ (size_t)ROWS * DM ];
static __device__ __nv_bfloat16 g_sl [ (size_t)ROWS * DM ];
static __device__ __nv_bfloat16 g_xh [ (size_t)ROWS * DM ];
static __device__ __nv_bfloat16 g_xl [ (size_t)ROWS * DM ];
static __device__ __nv_bfloat16 g_h1h[ (size_t)ROWS * DF ];
static __device__ __nv_bfloat16 g_h1l[ (size_t)ROWS * DF ];

// weights (concatenated)
#define WOFF_V    0
#define WOFF_O    65536
#define WOFF_A    131072
#define WOFF_OUT  163840
#define WOFF_1    229376
#define WOFF_2    491520
#define WTOT      753664
static __device__ __nv_bfloat16 g_wbh[WTOT];
static __device__ __nv_bfloat16 g_wbl[WTOT];

// ---------------- helpers ----------------
__device__ __forceinline__ uint32_t smem_to_u32(const void* p) {
    uint32_t a;
    asm("{ .reg .u64 t; cvta.to.shared.u64 t, %1; cvt.u32.u64 %0, t; }" : "=r"(a) : "l"(p));
    return a;
}

#define LDSM_X4(r, addr) \
    asm volatile("ldmatrix.sync.aligned.m8n8.x4.shared.b16 {%0,%1,%2,%3}, [%4];" \
        : "=r"((r)[0]), "=r"((r)[1]), "=r"((r)[2]), "=r"((r)[3]) : "r"(addr))

#define MMA_BF16(d, a, b) \
    asm volatile("mma.sync.aligned.m16n8k16.row.col.f32.bf16.bf16.f32 " \
        "{%0,%1,%2,%3}, {%4,%5,%6,%7}, {%8,%9}, {%0,%1,%2,%3};" \
        : "+f"((d)[0]), "+f"((d)[1]), "+f"((d)[2]), "+f"((d)[3]) \
        : "r"((a)[0]), "r"((a)[1]), "r"((a)[2]), "r"((a)[3]), \
          "r"((b)[0]), "r"((b)[1]))

#define STS128(r0, r1, r2, r3, smem_addr) \
    asm volatile("st.shared.v4.b32 [%0], {%1, %2, %3, %4};" \
        :: "r"(smem_addr), "r"(r0), "r"(r1), "r"(r2), "r"(r3) : "memory")

// swizzled byte offset within a 128-row x 128-byte tile
__device__ __forceinline__ uint32_t swz(uint32_t row, uint32_t kb) {
    return row * 128u + (kb ^ ((row & 7u) << 4));
}

__device__ __forceinline__ void split_bf16(float x, __nv_bfloat16& h, __nv_bfloat16& l) {
    h = __float2bfloat16(x);
    l = __float2bfloat16(x - __bfloat162float(h));
}

// ---------------- warp-MMA split-bf16 GEMM ----------------
// C[M,N] = A[M,K] @ B[N,K]^T + bias ; A,B as hi/lo bf16 pairs (K-major).
// Tile 128x128, BK=64, 256 threads (8 warps, 4m x 2n), warp tile 32x64.
// Dynamic smem: 4 x 16KB = 64KB (Ah, Al, Bh, Bl), single-buffered.
#define GSM_AH 0
#define GSM_AL 16384
#define GSM_BH 32768
#define GSM_BL 49152
#define GSM_TOTAL 65536

extern __shared__ char dyn_smem[];

__global__ void __launch_bounds__(256, 1)
mma_gemm_kernel(const __nv_bfloat16* __restrict__ Ah, const __nv_bfloat16* __restrict__ Al,
                const __nv_bfloat16* __restrict__ Bh, const __nv_bfloat16* __restrict__ Bl,
                const float* __restrict__ bias,
                float* __restrict__ C,
                __nv_bfloat16* __restrict__ Chi, __nv_bfloat16* __restrict__ Clo,
                int M, int N, int K, int relu)
{
    const uint32_t s0 = smem_to_u32(dyn_smem);
    const uint32_t sAH = s0 + GSM_AH, sAL = s0 + GSM_AL;
    const uint32_t sBH = s0 + GSM_BH, sBL = s0 + GSM_BL;
    const int tid  = threadIdx.x;
    const int wid  = tid >> 5;
    const int lane = tid & 31;
    const int wm   = wid & 3;    // 0..3  (m: 32 rows each)
    const int wn   = wid >> 2;   // 0..1  (n: 64 cols each)
    const int bm = blockIdx.y * 128;
    const int bn = blockIdx.x * 128;

    float acc[2][8][4];
#pragma unroll
    for (int i = 0; i < 2; i++)
#pragma unroll
        for (int j = 0; j < 8; j++)
#pragma unroll
            for (int c = 0; c < 4; c++) acc[i][j][c] = 0.f;

    const int nch = K >> 6;
    const uint4 z4 = make_uint4(0u, 0u, 0u, 0u);

    for (int ch = 0; ch < nch; ch++) {
        const int k0 = ch << 6;
        __syncthreads();   // previous iteration's ldmatrix reads done
#pragma unroll
        for (int t = 0; t < 4; t++) {
            int idx = t * 256 + tid;
            int row = idx >> 3, seg = idx & 7;
            uint32_t so = swz((uint32_t)row, (uint32_t)(seg * 16));
            int gm = bm + row;
            size_t aoff = (size_t)gm * K + k0 + seg * 8;
            size_t boff = (size_t)(bn + row) * K + k0 + seg * 8;
            uint4 vah = (gm < M) ? *(const uint4*)(Ah + aoff) : z4;
            uint4 val_ = (gm < M) ? *(const uint4*)(Al + aoff) : z4;
            uint4 vbh = *(const uint4*)(Bh + boff);
            uint4 vbl = *(const uint4*)(Bl + boff);
            STS128(vah.x, vah.y, vah.z, vah.w, sAH + so);
            STS128(val_.x, val_.y, val_.z, val_.w, sAL + so);
            STS128(vbh.x, vbh.y, vbh.z, vbh.w, sBH + so);
            STS128(vbl.x, vbl.y, vbl.z, vbl.w, sBL + so);
        }
        __syncthreads();

#pragma unroll
        for (int ks = 0; ks < 4; ks++) {
            // A fragments: rows wm*32 + mt*16 + (lane&15), kbyte ks*32 + (lane>>4)*16
            uint32_t a_h[2][4], a_l[2][4];
            {
                uint32_t rA = (uint32_t)(wm * 32 + (lane & 15));
                uint32_t kbA = (uint32_t)(ks * 32 + ((lane >> 4) << 4));
#pragma unroll
                for (int mt = 0; mt < 2; mt++) {
                    uint32_t off = swz(rA + mt * 16, kbA);
                    LDSM_X4(a_h[mt], sAH + off);
                    LDSM_X4(a_l[mt], sAL + off);
                }
            }
            // B fragments: x4 covers two n8k16 tiles
            uint32_t b_h[8][2], b_l[8][2];
            {
                uint32_t rB = (uint32_t)((lane & 7) + ((lane >> 4) << 3));
                uint32_t kbB = (uint32_t)(ks * 32 + (((lane >> 3) & 1) << 4));
#pragma unroll
                for (int np = 0; np < 4; np++) {
                    uint32_t row = (uint32_t)(wn * 64 + np * 16) + rB;
                    uint32_t off = swz(row, kbB);
                    uint32_t r4[4];
                    LDSM_X4(r4, sBH + off);
                    b_h[np * 2][0] = r4[0]; b_h[np * 2][1] = r4[1];
                    b_h[np * 2 + 1][0] = r4[2]; b_h[np * 2 + 1][1] = r4[3];
                    LDSM_X4(r4, sBL + off);
                    b_l[np * 2][0] = r4[0]; b_l[np * 2][1] = r4[1];
                    b_l[np * 2 + 1][0] = r4[2]; b_l[np * 2 + 1][1] = r4[3];
                }
            }
#pragma unroll
            for (int mt = 0; mt < 2; mt++)
#pragma unroll
                for (int nt = 0; nt < 8; nt++) {
                    MMA_BF16(acc[mt][nt], a_h[mt], b_h[nt]);
                    MMA_BF16(acc[mt][nt], a_l[mt], b_h[nt]);
                    MMA_BF16(acc[mt][nt], a_h[mt], b_l[nt]);
                }
        }
    }

    // epilogue
    const int mrow0 = bm + wm * 32;
    const int ncol0 = bn + wn * 64;
#pragma unroll
    for (int mt = 0; mt < 2; mt++) {
        int r0 = mrow0 + mt * 16 + (lane >> 2);
        int r1 = r0 + 8;
#pragma unroll
        for (int nt = 0; nt < 8; nt++) {
            int n = ncol0 + nt * 8 + (lane & 3) * 2;
            float bi0 = __ldg(&bias[n]), bi1 = __ldg(&bias[n + 1]);
            float v00 = acc[mt][nt][0] + bi0, v01 = acc[mt][nt][1] + bi1;
            float v10 = acc[mt][nt][2] + bi0, v11 = acc[mt][nt][3] + bi1;
            if (relu) {
                v00 = fmaxf(v00, 0.f); v01 = fmaxf(v01, 0.f);
                v10 = fmaxf(v10, 0.f); v11 = fmaxf(v11, 0.f);
            }
            if (C) {
                if (r0 < M) *(float2*)(C + (size_t)r0 * N + n) = make_float2(v00, v01);
                if (r1 < M) *(float2*)(C + (size_t)r1 * N + n) = make_float2(v10, v11);
            } else {
                __nv_bfloat16 h0, l0, h1, l1;
                if (r0 < M) {
                    split_bf16(v00, h0, l0); split_bf16(v01, h1, l1);
                    *(__nv_bfloat162*)(Chi + (size_t)r0 * N + n) = __nv_bfloat162(h0, h1);
                    *(__nv_bfloat162*)(Clo + (size_t)r0 * N + n) = __nv_bfloat162(l0, l1);
                }
                if (r1 < M) {
                    split_bf16(v10, h0, l0); split_bf16(v11, h1, l1);
                    *(__nv_bfloat162*)(Chi + (size_t)r1 * N + n) = __nv_bfloat162(h0, h1);
                    *(__nv_bfloat162*)(Clo + (size_t)r1 * N + n) = __nv_bfloat162(l0, l1);
                }
            }
        }
    }
}

// ---------------- build q and v_in (+ bf16 splits) ----------------
__global__ void build_qv_kernel(const float* __restrict__ src,
                                const float* __restrict__ pos,
                                const float* __restrict__ sel_vt)
{
    size_t idx = (size_t)blockIdx.x * blockDim.x + threadIdx.x;
    size_t total = (size_t)ROWS * DM;
    if (idx >= total) return;
    size_t row = idx / DM;
    int d = (int)(idx % DM);
    int n = (int)(row / LQ);
    int r = (int)(row % LQ);
    float qv, vv;
    if (r < L_SP) {
        size_t si = ((size_t)n * L_SP + r) * DM + d;
        float s = src[si];
        qv = s + pos[si];
        vv = s;
    } else {
        size_t si = ((size_t)n * N_VT + (r - L_SP)) * DM + d;
        float s = sel_vt[si];
        qv = s; vv = s;
    }
    g_v[idx] = vv;
    __nv_bfloat16 h, l;
    split_bf16(qv, h, l); g_qh[idx] = h; g_ql[idx] = l;
    split_bf16(vv, h, l); g_vh[idx] = h; g_vl[idx] = l;
}

// ---------------- weight split conversion ----------------
__global__ void conv_split_kernel(const float* __restrict__ X,
                                  __nv_bfloat16* __restrict__ H,
                                  __nv_bfloat16* __restrict__ L, int n)
{
    int i = blockIdx.x * blockDim.x + threadIdx.x;
    if (i >= n) return;
    __nv_bfloat16 h, l;
    split_bf16(X[i], h, l);
    H[i] = h; L[i] = l;
}

// ---------------- softmax over 16 points per (row, head) ----------------
__global__ void softmax16_kernel()
{
    int t = blockIdx.x * blockDim.x + threadIdx.x;
    if (t >= ROWS * NH) return;
    size_t base = (size_t)(t >> 3) * 128 + (t & 7) * 16;
    float v[16];
    float mx = -1e30f;
#pragma unroll
    for (int i = 0; i < 16; i++) { v[i] = g_attn[base + i]; mx = fmaxf(mx, v[i]); }
    float s = 0.f;
#pragma unroll
    for (int i = 0; i < 16; i++) { v[i] = __expf(v[i] - mx); s += v[i]; }
    float inv = 1.f / s;
#pragma unroll
    for (int i = 0; i < 16; i++) g_attn[base + i] = v[i] * inv;
}

// ---------------- deformable sampling -> bf16 hi/lo ----------------
__global__ void sample_kernel(const float* __restrict__ ref)
{
    const int row = blockIdx.x;
    const int m   = threadIdx.x >> 5;
    const int d   = threadIdx.x & 31;
    const int n   = row / LQ;

    const float* refp = ref + (size_t)row * (NLEV * 2);
    const float* offp = g_off + (size_t)row * DM + m * (NLEV * NPTS * 2);
    const float* attp = g_attn + (size_t)row * 128 + m * 16;
    const float* valn = g_val + (size_t)n * LQ * DM;

    float acc = 0.f;
#pragma unroll
    for (int l = 0; l < NLEV; l++) {
        const int H = c_H[l], W = c_W[l], st = c_start[l];
        const float rx = refp[l * 2 + 0];
        const float ry = refp[l * 2 + 1];
#pragma unroll
        for (int p = 0; p < NPTS; p++) {
            const float ox = offp[(l * NPTS + p) * 2 + 0];
            const float oy = offp[(l * NPTS + p) * 2 + 1];
            const float a  = attp[l * NPTS + p];
            const float x = rx * W + ox - 0.5f;
            const float y = ry * H + oy - 0.5f;
            const float x0f = floorf(x), y0f = floorf(y);
            const float wx = x - x0f, wy = y - y0f;
            const int x0 = (int)x0f, y0 = (int)y0f;
            const int x1 = x0 + 1,   y1 = y0 + 1;
            const bool vx0 = (x0 >= 0) & (x0 < W);
            const bool vx1 = (x1 >= 0) & (x1 < W);
            const bool vy0 = (y0 >= 0) & (y0 < H);
            const bool vy1 = (y1 >= 0) & (y1 < H);
            const float w00 = (1.f - wx) * (1.f - wy);
            const float w10 = wx * (1.f - wy);
            const float w01 = (1.f - wx) * wy;
            const float w11 = wx * wy;
            if (vx0 & vy0) acc += a * w00 * valn[((size_t)(st + y0 * W + x0)) * DM + m * DH + d];
            if (vx1 & vy0) acc += a * w10 * valn[((size_t)(st + y0 * W + x1)) * DM + m * DH + d];
            if (vx0 & vy1) acc += a * w01 * valn[((size_t)(st + y1 * W + x0)) * DM + m * DH + d];
            if (vx1 & vy1) acc += a * w11 * valn[((size_t)(st + y1 * W + x1)) * DM + m * DH + d];
        }
    }
    __nv_bfloat16 h, l;
    split_bf16(acc, h, l);
    size_t oi = (size_t)row * DM + m * DH + d;
    g_sh[oi] = h; g_sl[oi] = l;
}

// ---------------- residual + LayerNorm (+ optional bf16 split out) ----------------
__global__ void resid_ln_kernel(const float* __restrict__ a,
                                const float* __restrict__ b,
                                const float* __restrict__ g,
                                const float* __restrict__ beta,
                                float* __restrict__ out,
                                __nv_bfloat16* __restrict__ outH,
                                __nv_bfloat16* __restrict__ outL)
{
    __shared__ float red[64];
    const int row = blockIdx.x;
    const int t = threadIdx.x;
    size_t base = (size_t)row * DM;
    float x = a[base + t] + b[base + t];

    float s = x;
#pragma unroll
    for (int o = 16; o > 0; o >>= 1) s += __shfl_xor_sync(0xffffffffu, s, o);
    if ((t & 31) == 0) red[t >> 5] = s;
    __syncthreads();
    if (t < 8) {
        float v = red[t];
#pragma unroll
        for (int o = 4; o > 0; o >>= 1) v += __shfl_xor_sync(0xffu, v, o);
        if (t == 0) red[32] = v;
    }
    __syncthreads();
    float mean = red[32] * (1.f / DM);

    float xc = x - mean;
    float sq = xc * xc;
#pragma unroll
    for (int o = 16; o > 0; o >>= 1) sq += __shfl_xor_sync(0xffffffffu, sq, o);
    if ((t & 31) == 0) red[t >> 5] = sq;
    __syncthreads();
    if (t < 8) {
        float v = red[t];
#pragma unroll
        for (int o = 4; o > 0; o >>= 1) v += __shfl_xor_sync(0xffu, v, o);
        if (t == 0) red[33] = v;
    }
    __syncthreads();
    float var = red[33] * (1.f / DM);
    float inv = rsqrtf(var + EPSLN);
    float y = g[t] * xc * inv + beta[t];
    out[base + t] = y;
    if (outH) {
        __nv_bfloat16 h, l;
        split_bf16(y, h, l);
        outH[base + t] = h; outL[base + t] = l;
    }
}

// ---------------- assemble final output ----------------
__global__ void write_out_kernel(const float* __restrict__ all_vt, float* __restrict__ out)
{
    const size_t P1 = (size_t)NB * L_SP * DM;
    const size_t P2 = (size_t)NB * 75 * N_VT * DM;
    const size_t P3 = (size_t)NB * N_VT * DM;
    size_t idx = (size_t)blockIdx.x * blockDim.x + threadIdx.x;
    if (idx < P1) {
        size_t row = idx / DM; int d = (int)(idx % DM);
        int n = (int)(row / L_SP), r = (int)(row % L_SP);
        out[idx] = g_x[((size_t)n * LQ + r) * DM + d];
    } else if (idx < P1 + P2) {
        out[idx] = all_vt[idx - P1];
    } else if (idx < P1 + P2 + P3) {
        size_t k = idx - P1 - P2;
        size_t row = k / DM; int d = (int)(k % DM);
        int n = (int)(row / N_VT), r = (int)(row % N_VT);
        out[idx] = g_x[((size_t)n * LQ + L_SP + r) * DM + d];
    }
}

// ---------------- launch ----------------
extern "C" void kernel_launch(void* const* d_in, const int* in_sizes, int n_in,
                              void* d_out, int out_size)
{
    const float* src     = (const float*)d_in[0];
    const float* pos     = (const float*)d_in[1];
    const float* refpts  = (const float*)d_in[2];
    const float* all_vt  = (const float*)d_in[6];
    const float* sel_vt  = (const float*)d_in[7];
    const float* W_value = (const float*)d_in[8];
    const float* b_value = (const float*)d_in[9];
    const float* W_off   = (const float*)d_in[10];
    const float* b_off   = (const float*)d_in[11];
    const float* W_attn  = (const float*)d_in[12];
    const float* b_attn  = (const float*)d_in[13];
    const float* W_out   = (const float*)d_in[14];
    const float* b_out   = (const float*)d_in[15];
    const float* g1      = (const float*)d_in[16];
    const float* beta1   = (const float*)d_in[17];
    const float* W1      = (const float*)d_in[18];
    const float* bf1     = (const float*)d_in[19];
    const float* W2      = (const float*)d_in[20];
    const float* bf2     = (const float*)d_in[21];
    const float* g2      = (const float*)d_in[22];
    const float* beta2   = (const float*)d_in[23];
    float* out = (float*)d_out;

    float* p_v;    cudaGetSymbolAddress((void**)&p_v,    g_v);
    float* p_val;  cudaGetSymbolAddress((void**)&p_val,  g_val);
    float* p_off;  cudaGetSymbolAddress((void**)&p_off,  g_off);
    float* p_attn; cudaGetSymbolAddress((void**)&p_attn, g_attn);
    float* p_tmp;  cudaGetSymbolAddress((void**)&p_tmp,  g_tmp);
    float* p_x;    cudaGetSymbolAddress((void**)&p_x,    g_x);
    __nv_bfloat16 *p_qh, *p_ql, *p_vh, *p_vl, *p_sh, *p_sl, *p_xh, *p_xl, *p_h1h, *p_h1l, *p_wbh, *p_wbl;
    cudaGetSymbolAddress((void**)&p_qh,  g_qh);
    cudaGetSymbolAddress((void**)&p_ql,  g_ql);
    cudaGetSymbolAddress((void**)&p_vh,  g_vh);
    cudaGetSymbolAddress((void**)&p_vl,  g_vl);
    cudaGetSymbolAddress((void**)&p_sh,  g_sh);
    cudaGetSymbolAddress((void**)&p_sl,  g_sl);
    cudaGetSymbolAddress((void**)&p_xh,  g_xh);
    cudaGetSymbolAddress((void**)&p_xl,  g_xl);
    cudaGetSymbolAddress((void**)&p_h1h, g_h1h);
    cudaGetSymbolAddress((void**)&p_h1l, g_h1l);
    cudaGetSymbolAddress((void**)&p_wbh, g_wbh);
    cudaGetSymbolAddress((void**)&p_wbl, g_wbl);

    static int smem_set = 0;
    if (!smem_set) {
        cudaFuncSetAttribute(mma_gemm_kernel, cudaFuncAttributeMaxDynamicSharedMemorySize, GSM_TOTAL);
        smem_set = 1;
    }

    const int M = ROWS;
    const int MT = (M + 127) / 128;   // 171

    // 1. build q, v (with bf16 splits)
    {
        size_t total = (size_t)ROWS * DM;
        build_qv_kernel<<<(unsigned)((total + 255) / 256), 256>>>(src, pos, sel_vt);
    }
    // 2. weight conversions
    conv_split_kernel<<<(65536 + 255) / 256, 256>>>(W_value, p_wbh + WOFF_V,   p_wbl + WOFF_V,   65536);
    conv_split_kernel<<<(65536 + 255) / 256, 256>>>(W_off,   p_wbh + WOFF_O,   p_wbl + WOFF_O,   65536);
    conv_split_kernel<<<(32768 + 255) / 256, 256>>>(W_attn,  p_wbh + WOFF_A,   p_wbl + WOFF_A,   32768);
    conv_split_kernel<<<(65536 + 255) / 256, 256>>>(W_out,   p_wbh + WOFF_OUT, p_wbl + WOFF_OUT, 65536);
    conv_split_kernel<<<(262144 + 255) / 256, 256>>>(W1,     p_wbh + WOFF_1,   p_wbl + WOFF_1,   262144);
    conv_split_kernel<<<(262144 + 255) / 256, 256>>>(W2,     p_wbh + WOFF_2,   p_wbl + WOFF_2,   262144);

    // 3. value projection
    mma_gemm_kernel<<<dim3(2, MT), 256, GSM_TOTAL>>>(p_vh, p_vl, p_wbh + WOFF_V, p_wbl + WOFF_V,
                                                     b_value, p_val, nullptr, nullptr, M, DM, DM, 0);
    // 4. offsets
    mma_gemm_kernel<<<dim3(2, MT), 256, GSM_TOTAL>>>(p_qh, p_ql, p_wbh + WOFF_O, p_wbl + WOFF_O,
                                                     b_off, p_off, nullptr, nullptr, M, DM, DM, 0);
    // 5. attn logits (N=128)
    mma_gemm_kernel<<<dim3(1, MT), 256, GSM_TOTAL>>>(p_qh, p_ql, p_wbh + WOFF_A, p_wbl + WOFF_A,
                                                     b_attn, p_attn, nullptr, nullptr, M, 128, DM, 0);
    // 6. softmax
    softmax16_kernel<<<(ROWS * NH + 255) / 256, 256>>>();
    // 7. deformable sampling -> bf16 splits
    sample_kernel<<<ROWS, 256>>>(refpts);
    // 8. output projection -> g_tmp
    mma_gemm_kernel<<<dim3(2, MT), 256, GSM_TOTAL>>>(p_sh, p_sl, p_wbh + WOFF_OUT, p_wbl + WOFF_OUT,
                                                     b_out, p_tmp, nullptr, nullptr, M, DM, DM, 0);
    // 9. x = LN(v + src2) (+ bf16 splits)
    resid_ln_kernel<<<ROWS, 256>>>(p_v, p_tmp, g1, beta1, p_x, p_xh, p_xl);
    // 10. h1 = relu(x @ W1^T + bf1) -> bf16 splits directly
    mma_gemm_kernel<<<dim3(8, MT), 256, GSM_TOTAL>>>(p_xh, p_xl, p_wbh + WOFF_1, p_wbl + WOFF_1,
                                                     bf1, nullptr, p_h1h, p_h1l, M, DF, DM, 1);
    // 11. h = h1 @ W2^T + bf2 -> g_tmp (K=1024)
    mma_gemm_kernel<<<dim3(2, MT), 256, GSM_TOTAL>>>(p_h1h, p_h1l, p_wbh + WOFF_2, p_wbl + WOFF_2,
                                                     bf2, p_tmp, nullptr, nullptr, M, DM, DF, 0);
    // 12. x = LN(x + h)
    resid_ln_kernel<<<ROWS, 256>>>(p_x, p_tmp, g2, beta2, p_x, nullptr, nullptr);
    // 13. assemble outputs
    {
        size_t total = (size_t)NB * (L_SP + 75 * N_VT + N_VT) * DM;
        write_out_kernel<<<(unsigned)((total + 255) / 256), 256>>>(all_vt, out);
    }
}

// round 5
// speedup vs baseline: 2.4749x; 1.0847x over previous
#include <cuda_runtime.h>
#include <cuda_bf16.h>
#include <math.h>
#include <cstdint>

// ---------------- problem constants ----------------
#define NB     4
#define L_SP   5440
#define N_VT   8
#define LQ     (L_SP + N_VT)      // 5448
#define DM     256
#define DF     1024
#define NH     8
#define DH     32
#define NLEV   4
#define NPTS   4
#define ROWS   (NB * LQ)          // 21792
#define EPSLN  1e-5f

__device__ __constant__ int c_H[NLEV]     = {64, 32, 16, 8};
__device__ __constant__ int c_W[NLEV]     = {64, 32, 16, 8};
__device__ __constant__ int c_start[NLEV] = {0, 4096, 5120, 5376};

// ---------------- scratch (device globals; no allocs) ----------------
static __device__ float g_v   [ (size_t)ROWS * DM ];
static __device__ float g_val [ (size_t)ROWS * DM ];
static __device__ float g_off [ (size_t)ROWS * DM ];
static __device__ float g_attn[ (size_t)ROWS * 128 ];
static __device__ float g_tmp [ (size_t)ROWS * DM ];
static __device__ float g_x   [ (size_t)ROWS * DM ];

static __device__ __nv_bfloat16 g_qh [ (size_t)ROWS * DM ];
static __device__ __nv_bfloat16 g_ql [ (size_t)ROWS * DM ];
static __device__ __nv_bfloat16 g_vh [ (size_t)ROWS * DM ];
static __device__ __nv_bfloat16 g_vl [ (size_t)ROWS * DM ];
static __device__ __nv_bfloat16 g_sh [ (size_t)ROWS * DM ];
static __device__ __nv_bfloat16 g_sl [ (size_t)ROWS * DM ];
static __device__ __nv_bfloat16 g_xh [ (size_t)ROWS * DM ];
static __device__ __nv_bfloat16 g_xl [ (size_t)ROWS * DM ];
static __device__ __nv_bfloat16 g_h1h[ (size_t)ROWS * DF ];
static __device__ __nv_bfloat16 g_h1l[ (size_t)ROWS * DF ];

// weights (concatenated): Wv | Wo | Wa | Wout | W1 | W2  (Wo,Wa adjacent -> fused OA GEMM)
#define WOFF_V    0
#define WOFF_O    65536
#define WOFF_A    131072
#define WOFF_OUT  163840
#define WOFF_1    229376
#define WOFF_2    491520
#define WTOT      753664
static __device__ __nv_bfloat16 g_wbh[WTOT];
static __device__ __nv_bfloat16 g_wbl[WTOT];

// ---------------- helpers ----------------
__device__ __forceinline__ uint32_t smem_to_u32(const void* p) {
    uint32_t a;
    asm("{ .reg .u64 t; cvta.to.shared.u64 t, %1; cvt.u32.u64 %0, t; }" : "=r"(a) : "l"(p));
    return a;
}

#define LDSM_X4(r, addr) \
    asm volatile("ldmatrix.sync.aligned.m8n8.x4.shared.b16 {%0,%1,%2,%3}, [%4];" \
        : "=r"((r)[0]), "=r"((r)[1]), "=r"((r)[2]), "=r"((r)[3]) : "r"(addr))

#define MMA_BF16(d, a, b) \
    asm volatile("mma.sync.aligned.m16n8k16.row.col.f32.bf16.bf16.f32 " \
        "{%0,%1,%2,%3}, {%4,%5,%6,%7}, {%8,%9}, {%0,%1,%2,%3};" \
        : "+f"((d)[0]), "+f"((d)[1]), "+f"((d)[2]), "+f"((d)[3]) \
        : "r"((a)[0]), "r"((a)[1]), "r"((a)[2]), "r"((a)[3]), \
          "r"((b)[0]), "r"((b)[1]))

__device__ __forceinline__ void cp_async16(uint32_t dst, const void* src, bool pred) {
    int sz = pred ? 16 : 0;
    asm volatile("cp.async.cg.shared.global [%0], [%1], 16, %2;"
        :: "r"(dst), "l"(src), "r"(sz) : "memory");
}
#define CP_COMMIT() asm volatile("cp.async.commit_group;" ::: "memory")
#define CP_WAIT2()  asm volatile("cp.async.wait_group 2;" ::: "memory")

// swizzled byte offset within a 128-row x 128-byte tile
__device__ __forceinline__ uint32_t swz(uint32_t row, uint32_t kb) {
    return row * 128u + (kb ^ ((row & 7u) << 4));
}

__device__ __forceinline__ void split_bf16(float x, __nv_bfloat16& h, __nv_bfloat16& l) {
    h = __float2bfloat16(x);
    l = __float2bfloat16(x - __bfloat162float(h));
}

// ---------------- pipelined warp-MMA split-bf16 GEMM ----------------
// C = A @ B^T + bias. Tile 128x128, BK=64, 256 threads (8 warps, 4m x 2n).
// 3-stage cp.async pipeline; per stage 64KB (AH/AL/BH/BL 16KB each).
#define STG_BYTES 65536
#define SB_AH 0
#define SB_AL 16384
#define SB_BH 32768
#define SB_BL 49152
#define GSM_TOTAL (3 * STG_BYTES)   // 196608

extern __shared__ char dyn_smem[];

__device__ __forceinline__ void gemm_issue_stage(
    uint32_t sb, const __nv_bfloat16* Ah, const __nv_bfloat16* Al,
    const __nv_bfloat16* Bh, const __nv_bfloat16* Bl,
    int bm, int bn, int k0, int M, int K, int tid, bool active)
{
#pragma unroll
    for (int t = 0; t < 4; t++) {
        int idx = t * 256 + tid;
        int row = idx >> 3, seg = idx & 7;
        uint32_t so = swz((uint32_t)row, (uint32_t)(seg * 16));
        int gm = bm + row;
        bool am = active && (gm < M);
        size_t aoff = am ? ((size_t)gm * K + k0 + seg * 8) : 0;
        size_t boff = (size_t)(bn + row) * K + k0 + seg * 8;
        cp_async16(sb + SB_AH + so, Ah + aoff, am);
        cp_async16(sb + SB_AL + so, Al + aoff, am);
        cp_async16(sb + SB_BH + so, Bh + boff, active);
        cp_async16(sb + SB_BL + so, Bl + boff, active);
    }
}

__global__ void __launch_bounds__(256, 1)
mma_gemm_kernel(const __nv_bfloat16* __restrict__ Ah, const __nv_bfloat16* __restrict__ Al,
                const __nv_bfloat16* __restrict__ Bh, const __nv_bfloat16* __restrict__ Bl,
                const float* __restrict__ bias1, const float* __restrict__ bias2,
                float* __restrict__ C, float* __restrict__ C2,
                __nv_bfloat16* __restrict__ Chi, __nv_bfloat16* __restrict__ Clo,
                int M, int N1, int K, int relu)
{
    const uint32_t s0 = smem_to_u32(dyn_smem);
    const int tid  = threadIdx.x;
    const int wid  = tid >> 5;
    const int lane = tid & 31;
    const int wm   = wid & 3;
    const int wn   = wid >> 2;
    const int bm = blockIdx.y * 128;
    const int bn = blockIdx.x * 128;
    const int Ntot = gridDim.x * 128;

    float acc[2][8][4];
#pragma unroll
    for (int i = 0; i < 2; i++)
#pragma unroll
        for (int j = 0; j < 8; j++)
#pragma unroll
            for (int c = 0; c < 4; c++) acc[i][j][c] = 0.f;

    const int nch = K >> 6;

    // prologue: fill 3 stages
#pragma unroll
    for (int s = 0; s < 3; s++) {
        gemm_issue_stage(s0 + s * STG_BYTES, Ah, Al, Bh, Bl, bm, bn, s << 6, M, K, tid, s < nch);
        CP_COMMIT();
    }

    for (int ch = 0; ch < nch; ch++) {
        CP_WAIT2();
        __syncthreads();
        const uint32_t sb = s0 + (ch % 3) * STG_BYTES;
        const uint32_t sAH = sb + SB_AH, sAL = sb + SB_AL;
        const uint32_t sBH = sb + SB_BH, sBL = sb + SB_BL;

#pragma unroll
        for (int ks = 0; ks < 4; ks++) {
            uint32_t a_h[2][4], a_l[2][4];
            {
                uint32_t rA = (uint32_t)(wm * 32 + (lane & 15));
                uint32_t kbA = (uint32_t)(ks * 32 + ((lane >> 4) << 4));
#pragma unroll
                for (int mt = 0; mt < 2; mt++) {
                    uint32_t off = swz(rA + mt * 16, kbA);
                    LDSM_X4(a_h[mt], sAH + off);
                    LDSM_X4(a_l[mt], sAL + off);
                }
            }
            uint32_t b_h[8][2], b_l[8][2];
            {
                uint32_t rB = (uint32_t)((lane & 7) + ((lane >> 4) << 3));
                uint32_t kbB = (uint32_t)(ks * 32 + (((lane >> 3) & 1) << 4));
#pragma unroll
                for (int np = 0; np < 4; np++) {
                    uint32_t row = (uint32_t)(wn * 64 + np * 16) + rB;
                    uint32_t off = swz(row, kbB);
                    uint32_t r4[4];
                    LDSM_X4(r4, sBH + off);
                    b_h[np * 2][0] = r4[0]; b_h[np * 2][1] = r4[1];
                    b_h[np * 2 + 1][0] = r4[2]; b_h[np * 2 + 1][1] = r4[3];
                    LDSM_X4(r4, sBL + off);
                    b_l[np * 2][0] = r4[0]; b_l[np * 2][1] = r4[1];
                    b_l[np * 2 + 1][0] = r4[2]; b_l[np * 2 + 1][1] = r4[3];
                }
            }
#pragma unroll
            for (int mt = 0; mt < 2; mt++)
#pragma unroll
                for (int nt = 0; nt < 8; nt++) {
                    MMA_BF16(acc[mt][nt], a_h[mt], b_h[nt]);
                    MMA_BF16(acc[mt][nt], a_l[mt], b_h[nt]);
                    MMA_BF16(acc[mt][nt], a_h[mt], b_l[nt]);
                }
        }
        __syncthreads();
        int nxt = ch + 3;
        gemm_issue_stage(s0 + (nxt % 3) * STG_BYTES, Ah, Al, Bh, Bl,
                         bm, bn, nxt << 6, M, K, tid, nxt < nch);
        CP_COMMIT();
    }

    // epilogue
    const int mrow0 = bm + wm * 32;
    const int ncol0 = bn + wn * 64;
#pragma unroll
    for (int mt = 0; mt < 2; mt++) {
        int r0 = mrow0 + mt * 16 + (lane >> 2);
        int r1 = r0 + 8;
#pragma unroll
        for (int nt = 0; nt < 8; nt++) {
            int n = ncol0 + nt * 8 + (lane & 3) * 2;
            // column demux for fused output (C2)
            float* dst; int stride; int nc;
            float bi0, bi1;
            if (C2 && n >= N1) {
                nc = n - N1; dst = C2; stride = Ntot - N1;
                bi0 = __ldg(&bias2[nc]); bi1 = __ldg(&bias2[nc + 1]);
            } else {
                nc = n; dst = C; stride = N1;
                bi0 = __ldg(&bias1[nc]); bi1 = __ldg(&bias1[nc + 1]);
            }
            float v00 = acc[mt][nt][0] + bi0, v01 = acc[mt][nt][1] + bi1;
            float v10 = acc[mt][nt][2] + bi0, v11 = acc[mt][nt][3] + bi1;
            if (relu) {
                v00 = fmaxf(v00, 0.f); v01 = fmaxf(v01, 0.f);
                v10 = fmaxf(v10, 0.f); v11 = fmaxf(v11, 0.f);
            }
            if (dst) {
                if (r0 < M) *(float2*)(dst + (size_t)r0 * stride + nc) = make_float2(v00, v01);
                if (r1 < M) *(float2*)(dst + (size_t)r1 * stride + nc) = make_float2(v10, v11);
            } else {
                __nv_bfloat16 h0, l0, h1, l1;
                if (r0 < M) {
                    split_bf16(v00, h0, l0); split_bf16(v01, h1, l1);
                    *(__nv_bfloat162*)(Chi + (size_t)r0 * Ntot + n) = __nv_bfloat162(h0, h1);
                    *(__nv_bfloat162*)(Clo + (size_t)r0 * Ntot + n) = __nv_bfloat162(l0, l1);
                }
                if (r1 < M) {
                    split_bf16(v10, h0, l0); split_bf16(v11, h1, l1);
                    *(__nv_bfloat162*)(Chi + (size_t)r1 * Ntot + n) = __nv_bfloat162(h0, h1);
                    *(__nv_bfloat162*)(Clo + (size_t)r1 * Ntot + n) = __nv_bfloat162(l0, l1);
                }
            }
        }
    }
}

// ---------------- build q and v_in (+ bf16 splits) ----------------
__global__ void build_qv_kernel(const float* __restrict__ src,
                                const float* __restrict__ pos,
                                const float* __restrict__ sel_vt)
{
    size_t idx = (size_t)blockIdx.x * blockDim.x + threadIdx.x;
    size_t total = (size_t)ROWS * DM;
    if (idx >= total) return;
    size_t row = idx / DM;
    int d = (int)(idx % DM);
    int n = (int)(row / LQ);
    int r = (int)(row % LQ);
    float qv, vv;
    if (r < L_SP) {
        size_t si = ((size_t)n * L_SP + r) * DM + d;
        float s = src[si];
        qv = s + pos[si];
        vv = s;
    } else {
        size_t si = ((size_t)n * N_VT + (r - L_SP)) * DM + d;
        float s = sel_vt[si];
        qv = s; vv = s;
    }
    g_v[idx] = vv;
    __nv_bfloat16 h, l;
    split_bf16(qv, h, l); g_qh[idx] = h; g_ql[idx] = l;
    split_bf16(vv, h, l); g_vh[idx] = h; g_vl[idx] = l;
}

// ---------------- all weight splits in ONE kernel ----------------
__global__ void conv_all_kernel(const float* __restrict__ Wv, const float* __restrict__ Wo,
                                const float* __restrict__ Wa, const float* __restrict__ Wout,
                                const float* __restrict__ W1, const float* __restrict__ W2)
{
    int i = blockIdx.x * blockDim.x + threadIdx.x;
    if (i >= WTOT) return;
    float x;
    if      (i < WOFF_O)   x = Wv  [i];
    else if (i < WOFF_A)   x = Wo  [i - WOFF_O];
    else if (i < WOFF_OUT) x = Wa  [i - WOFF_A];
    else if (i < WOFF_1)   x = Wout[i - WOFF_OUT];
    else if (i < WOFF_2)   x = W1  [i - WOFF_1];
    else                   x = W2  [i - WOFF_2];
    __nv_bfloat16 h, l;
    split_bf16(x, h, l);
    g_wbh[i] = h; g_wbl[i] = l;
}

// ---------------- softmax over 16 points per (row, head) ----------------
__global__ void softmax16_kernel()
{
    int t = blockIdx.x * blockDim.x + threadIdx.x;
    if (t >= ROWS * NH) return;
    size_t base = (size_t)(t >> 3) * 128 + (t & 7) * 16;
    float v[16];
    float mx = -1e30f;
#pragma unroll
    for (int i = 0; i < 16; i++) { v[i] = g_attn[base + i]; mx = fmaxf(mx, v[i]); }
    float s = 0.f;
#pragma unroll
    for (int i = 0; i < 16; i++) { v[i] = __expf(v[i] - mx); s += v[i]; }
    float inv = 1.f / s;
#pragma unroll
    for (int i = 0; i < 16; i++) g_attn[base + i] = v[i] * inv;
}

// ---------------- deformable sampling -> bf16 hi/lo ----------------
__global__ void sample_kernel(const float* __restrict__ ref)
{
    const int row = blockIdx.x;
    const int m   = threadIdx.x >> 5;
    const int d   = threadIdx.x & 31;
    const int n   = row / LQ;

    const float* refp = ref + (size_t)row * (NLEV * 2);
    const float* offp = g_off + (size_t)row * DM + m * (NLEV * NPTS * 2);
    const float* attp = g_attn + (size_t)row * 128 + m * 16;
    const float* valn = g_val + (size_t)n * LQ * DM;

    float acc = 0.f;
#pragma unroll
    for (int l = 0; l < NLEV; l++) {
        const int H = c_H[l], W = c_W[l], st = c_start[l];
        const float rx = refp[l * 2 + 0];
        const float ry = refp[l * 2 + 1];
#pragma unroll
        for (int p = 0; p < NPTS; p++) {
            const float ox = offp[(l * NPTS + p) * 2 + 0];
            const float oy = offp[(l * NPTS + p) * 2 + 1];
            const float a  = attp[l * NPTS + p];
            const float x = rx * W + ox - 0.5f;
            const float y = ry * H + oy - 0.5f;
            const float x0f = floorf(x), y0f = floorf(y);
            const float wx = x - x0f, wy = y - y0f;
            const int x0 = (int)x0f, y0 = (int)y0f;
            const int x1 = x0 + 1,   y1 = y0 + 1;
            const bool vx0 = (x0 >= 0) & (x0 < W);
            const bool vx1 = (x1 >= 0) & (x1 < W);
            const bool vy0 = (y0 >= 0) & (y0 < H);
            const bool vy1 = (y1 >= 0) & (y1 < H);
            const float w00 = (1.f - wx) * (1.f - wy);
            const float w10 = wx * (1.f - wy);
            const float w01 = (1.f - wx) * wy;
            const float w11 = wx * wy;
            if (vx0 & vy0) acc += a * w00 * valn[((size_t)(st + y0 * W + x0)) * DM + m * DH + d];
            if (vx1 & vy0) acc += a * w10 * valn[((size_t)(st + y0 * W + x1)) * DM + m * DH + d];
            if (vx0 & vy1) acc += a * w01 * valn[((size_t)(st + y1 * W + x0)) * DM + m * DH + d];
            if (vx1 & vy1) acc += a * w11 * valn[((size_t)(st + y1 * W + x1)) * DM + m * DH + d];
        }
    }
    __nv_bfloat16 h, l;
    split_bf16(acc, h, l);
    size_t oi = (size_t)row * DM + m * DH + d;
    g_sh[oi] = h; g_sl[oi] = l;
}

// ---------------- residual + LayerNorm (+ optional bf16 split out) ----------------
__global__ void resid_ln_kernel(const float* __restrict__ a,
                                const float* __restrict__ b,
                                const float* __restrict__ g,
                                const float* __restrict__ beta,
                                float* __restrict__ out,
                                __nv_bfloat16* __restrict__ outH,
                                __nv_bfloat16* __restrict__ outL)
{
    __shared__ float red[64];
    const int row = blockIdx.x;
    const int t = threadIdx.x;
    size_t base = (size_t)row * DM;
    float x = a[base + t] + b[base + t];

    float s = x;
#pragma unroll
    for (int o = 16; o > 0; o >>= 1) s += __shfl_xor_sync(0xffffffffu, s, o);
    if ((t & 31) == 0) red[t >> 5] = s;
    __syncthreads();
    if (t < 8) {
        float v = red[t];
#pragma unroll
        for (int o = 4; o > 0; o >>= 1) v += __shfl_xor_sync(0xffu, v, o);
        if (t == 0) red[32] = v;
    }
    __syncthreads();
    float mean = red[32] * (1.f / DM);

    float xc = x - mean;
    float sq = xc * xc;
#pragma unroll
    for (int o = 16; o > 0; o >>= 1) sq += __shfl_xor_sync(0xffffffffu, sq, o);
    if ((t & 31) == 0) red[t >> 5] = sq;
    __syncthreads();
    if (t < 8) {
        float v = red[t];
#pragma unroll
        for (int o = 4; o > 0; o >>= 1) v += __shfl_xor_sync(0xffu, v, o);
        if (t == 0) red[33] = v;
    }
    __syncthreads();
    float var = red[33] * (1.f / DM);
    float inv = rsqrtf(var + EPSLN);
    float y = g[t] * xc * inv + beta[t];
    out[base + t] = y;
    if (outH) {
        __nv_bfloat16 h, l;
        split_bf16(y, h, l);
        outH[base + t] = h; outL[base + t] = l;
    }
}

// ---------------- assemble final output ----------------
__global__ void write_out_kernel(const float* __restrict__ all_vt, float* __restrict__ out)
{
    const size_t P1 = (size_t)NB * L_SP * DM;
    const size_t P2 = (size_t)NB * 75 * N_VT * DM;
    const size_t P3 = (size_t)NB * N_VT * DM;
    size_t idx = (size_t)blockIdx.x * blockDim.x + threadIdx.x;
    if (idx < P1) {
        size_t row = idx / DM; int d = (int)(idx % DM);
        int n = (int)(row / L_SP), r = (int)(row % L_SP);
        out[idx] = g_x[((size_t)n * LQ + r) * DM + d];
    } else if (idx < P1 + P2) {
        out[idx] = all_vt[idx - P1];
    } else if (idx < P1 + P2 + P3) {
        size_t k = idx - P1 - P2;
        size_t row = k / DM; int d = (int)(k % DM);
        int n = (int)(row / N_VT), r = (int)(row % N_VT);
        out[idx] = g_x[((size_t)n * LQ + L_SP + r) * DM + d];
    }
}

// ---------------- launch ----------------
extern "C" void kernel_launch(void* const* d_in, const int* in_sizes, int n_in,
                              void* d_out, int out_size)
{
    const float* src     = (const float*)d_in[0];
    const float* pos     = (const float*)d_in[1];
    const float* refpts  = (const float*)d_in[2];
    const float* all_vt  = (const float*)d_in[6];
    const float* sel_vt  = (const float*)d_in[7];
    const float* W_value = (const float*)d_in[8];
    const float* b_value = (const float*)d_in[9];
    const float* W_off   = (const float*)d_in[10];
    const float* b_off   = (const float*)d_in[11];
    const float* W_attn  = (const float*)d_in[12];
    const float* b_attn  = (const float*)d_in[13];
    const float* W_out   = (const float*)d_in[14];
    const float* b_out   = (const float*)d_in[15];
    const float* g1      = (const float*)d_in[16];
    const float* beta1   = (const float*)d_in[17];
    const float* W1      = (const float*)d_in[18];
    const float* bf1     = (const float*)d_in[19];
    const float* W2      = (const float*)d_in[20];
    const float* bf2     = (const float*)d_in[21];
    const float* g2      = (const float*)d_in[22];
    const float* beta2   = (const float*)d_in[23];
    float* out = (float*)d_out;

    float* p_v;    cudaGetSymbolAddress((void**)&p_v,    g_v);
    float* p_val;  cudaGetSymbolAddress((void**)&p_val,  g_val);
    float* p_off;  cudaGetSymbolAddress((void**)&p_off,  g_off);
    float* p_attn; cudaGetSymbolAddress((void**)&p_attn, g_attn);
    float* p_tmp;  cudaGetSymbolAddress((void**)&p_tmp,  g_tmp);
    float* p_x;    cudaGetSymbolAddress((void**)&p_x,    g_x);
    __nv_bfloat16 *p_qh, *p_ql, *p_vh, *p_vl, *p_sh, *p_sl, *p_xh, *p_xl, *p_h1h, *p_h1l, *p_wbh, *p_wbl;
    cudaGetSymbolAddress((void**)&p_qh,  g_qh);
    cudaGetSymbolAddress((void**)&p_ql,  g_ql);
    cudaGetSymbolAddress((void**)&p_vh,  g_vh);
    cudaGetSymbolAddress((void**)&p_vl,  g_vl);
    cudaGetSymbolAddress((void**)&p_sh,  g_sh);
    cudaGetSymbolAddress((void**)&p_sl,  g_sl);
    cudaGetSymbolAddress((void**)&p_xh,  g_xh);
    cudaGetSymbolAddress((void**)&p_xl,  g_xl);
    cudaGetSymbolAddress((void**)&p_h1h, g_h1h);
    cudaGetSymbolAddress((void**)&p_h1l, g_h1l);
    cudaGetSymbolAddress((void**)&p_wbh, g_wbh);
    cudaGetSymbolAddress((void**)&p_wbl, g_wbl);

    static int smem_set = 0;
    if (!smem_set) {
        cudaFuncSetAttribute(mma_gemm_kernel, cudaFuncAttributeMaxDynamicSharedMemorySize, GSM_TOTAL);
        smem_set = 1;
    }

    const int M = ROWS;
    const int MT = (M + 127) / 128;   // 171

    // 1. build q, v (with bf16 splits)
    {
        size_t total = (size_t)ROWS * DM;
        build_qv_kernel<<<(unsigned)((total + 255) / 256), 256>>>(src, pos, sel_vt);
    }
    // 2. weight splits (single kernel)
    conv_all_kernel<<<(WTOT + 255) / 256, 256>>>(W_value, W_off, W_attn, W_out, W1, W2);

    // 3. value projection
    mma_gemm_kernel<<<dim3(2, MT), 256, GSM_TOTAL>>>(p_vh, p_vl, p_wbh + WOFF_V, p_wbl + WOFF_V,
        b_value, nullptr, p_val, nullptr, nullptr, nullptr, M, DM, DM, 0);
    // 4. fused offsets+attn: B = [Wo; Wa], N=384; cols<256 -> g_off, cols>=256 -> g_attn
    mma_gemm_kernel<<<dim3(3, MT), 256, GSM_TOTAL>>>(p_qh, p_ql, p_wbh + WOFF_O, p_wbl + WOFF_O,
        b_off, b_attn, p_off, p_attn, nullptr, nullptr, M, DM, DM, 0);
    // 5. softmax
    softmax16_kernel<<<(ROWS * NH + 255) / 256, 256>>>();
    // 6. deformable sampling -> bf16 splits
    sample_kernel<<<ROWS, 256>>>(refpts);
    // 7. output projection -> g_tmp
    mma_gemm_kernel<<<dim3(2, MT), 256, GSM_TOTAL>>>(p_sh, p_sl, p_wbh + WOFF_OUT, p_wbl + WOFF_OUT,
        b_out, nullptr, p_tmp, nullptr, nullptr, nullptr, M, DM, DM, 0);
    // 8. x = LN(v + src2) (+ bf16 splits)
    resid_ln_kernel<<<ROWS, 256>>>(p_v, p_tmp, g1, beta1, p_x, p_xh, p_xl);
    // 9. h1 = relu(x @ W1^T + bf1) -> bf16 splits directly
    mma_gemm_kernel<<<dim3(8, MT), 256, GSM_TOTAL>>>(p_xh, p_xl, p_wbh + WOFF_1, p_wbl + WOFF_1,
        bf1, nullptr, nullptr, nullptr, p_h1h, p_h1l, M, DF, DM, 1);
    // 10. h = h1 @ W2^T + bf2 -> g_tmp (K=1024)
    mma_gemm_kernel<<<dim3(2, MT), 256, GSM_TOTAL>>>(p_h1h, p_h1l, p_wbh + WOFF_2, p_wbl + WOFF_2,
        bf2, nullptr, p_tmp, nullptr, nullptr, nullptr, M, DM, DF, 0);
    // 11. x = LN(x + h)
    resid_ln_kernel<<<ROWS, 256>>>(p_x, p_tmp, g2, beta2, p_x, nullptr, nullptr);
    // 12. assemble outputs
    {
        size_t total = (size_t)NB * (L_SP + 75 * N_VT + N_VT) * DM;
        write_out_kernel<<<(unsigned)((total + 255) / 256), 256>>>(all_vt, out);
    }
}

// round 6
// speedup vs baseline: 2.8637x; 1.1571x over previous
#include <cuda_runtime.h>
#include <cuda_bf16.h>
#include <math.h>
#include <cstdint>

// ---------------- problem constants ----------------
#define NB     4
#define L_SP   5440
#define N_VT   8
#define LQ     (L_SP + N_VT)      // 5448
#define DM     256
#define DF     1024
#define NH     8
#define DH     32
#define NLEV   4
#define NPTS   4
#define ROWS   (NB * LQ)          // 21792
#define EPSLN  1e-5f

__device__ __constant__ int c_H[NLEV]     = {64, 32, 16, 8};
__device__ __constant__ int c_W[NLEV]     = {64, 32, 16, 8};
__device__ __constant__ int c_start[NLEV] = {0, 4096, 5120, 5376};

// ---------------- scratch (device globals; no allocs) ----------------
static __device__ float g_v   [ (size_t)ROWS * DM ];
static __device__ float g_val [ (size_t)ROWS * DM ];
static __device__ float g_off [ (size_t)ROWS * DM ];
static __device__ float g_attn[ (size_t)ROWS * 128 ];
static __device__ float g_tmp [ (size_t)ROWS * DM ];
static __device__ float g_x   [ (size_t)ROWS * DM ];

static __device__ __nv_bfloat16 g_qh [ (size_t)ROWS * DM ];
static __device__ __nv_bfloat16 g_ql [ (size_t)ROWS * DM ];
static __device__ __nv_bfloat16 g_vh [ (size_t)ROWS * DM ];
static __device__ __nv_bfloat16 g_vl [ (size_t)ROWS * DM ];
static __device__ __nv_bfloat16 g_sh [ (size_t)ROWS * DM ];
static __device__ __nv_bfloat16 g_sl [ (size_t)ROWS * DM ];
static __device__ __nv_bfloat16 g_xh [ (size_t)ROWS * DM ];
static __device__ __nv_bfloat16 g_xl [ (size_t)ROWS * DM ];
static __device__ __nv_bfloat16 g_h1h[ (size_t)ROWS * DF ];
static __device__ __nv_bfloat16 g_h1l[ (size_t)ROWS * DF ];

// weights (concatenated): Wv | Wo | Wa | Wout | W1 | W2
#define WOFF_V    0
#define WOFF_O    65536
#define WOFF_A    131072
#define WOFF_OUT  163840
#define WOFF_1    229376
#define WOFF_2    491520
#define WTOT      753664
static __device__ __nv_bfloat16 g_wbh[WTOT];
static __device__ __nv_bfloat16 g_wbl[WTOT];

// ---------------- helpers ----------------
__device__ __forceinline__ uint32_t smem_to_u32(const void* p) {
    uint32_t a;
    asm("{ .reg .u64 t; cvta.to.shared.u64 t, %1; cvt.u32.u64 %0, t; }" : "=r"(a) : "l"(p));
    return a;
}

#define LDSM_X4(r, addr) \
    asm volatile("ldmatrix.sync.aligned.m8n8.x4.shared.b16 {%0,%1,%2,%3}, [%4];" \
        : "=r"((r)[0]), "=r"((r)[1]), "=r"((r)[2]), "=r"((r)[3]) : "r"(addr))

#define MMA_BF16(d, a, b) \
    asm volatile("mma.sync.aligned.m16n8k16.row.col.f32.bf16.bf16.f32 " \
        "{%0,%1,%2,%3}, {%4,%5,%6,%7}, {%8,%9}, {%0,%1,%2,%3};" \
        : "+f"((d)[0]), "+f"((d)[1]), "+f"((d)[2]), "+f"((d)[3]) \
        : "r"((a)[0]), "r"((a)[1]), "r"((a)[2]), "r"((a)[3]), \
          "r"((b)[0]), "r"((b)[1]))

__device__ __forceinline__ void cp_async16(uint32_t dst, const void* src, bool pred) {
    int sz = pred ? 16 : 0;
    asm volatile("cp.async.cg.shared.global [%0], [%1], 16, %2;"
        :: "r"(dst), "l"(src), "r"(sz) : "memory");
}
#define CP_COMMIT() asm volatile("cp.async.commit_group;" ::: "memory")
#define CP_WAIT1()  asm volatile("cp.async.wait_group 1;" ::: "memory")

// swizzled byte offset within rows of 128 bytes
__device__ __forceinline__ uint32_t swz(uint32_t row, uint32_t kb) {
    return row * 128u + (kb ^ ((row & 7u) << 4));
}

__device__ __forceinline__ void split_bf16(float x, __nv_bfloat16& h, __nv_bfloat16& l) {
    h = __float2bfloat16(x);
    l = __float2bfloat16(x - __bfloat162float(h));
}

// ---------------- pipelined warp-MMA split-bf16 GEMM ----------------
// C = A @ B^T + bias. CTA tile 128x64, BK=64, 256 threads (8 warps, 4m x 2n),
// warp tile 32x32. 2-stage cp.async pipeline; stage = 48KB (AH 16K, AL 16K, BH 8K, BL 8K).
// 2 CTAs/SM (96KB smem, <=128 regs).
#define STG_BYTES 49152
#define SB_AH 0
#define SB_AL 16384
#define SB_BH 32768
#define SB_BL 40960
#define GSM_TOTAL (2 * STG_BYTES)   // 98304

extern __shared__ char dyn_smem[];

__device__ __forceinline__ void gemm_issue_stage(
    uint32_t sb, const __nv_bfloat16* Ah, const __nv_bfloat16* Al,
    const __nv_bfloat16* Bh, const __nv_bfloat16* Bl,
    int bm, int bn, int k0, int M, int K, int tid, bool active)
{
    // A: 128 rows x 8 segs = 1024 slots (4 iters)
#pragma unroll
    for (int t = 0; t < 4; t++) {
        int idx = t * 256 + tid;
        int row = idx >> 3, seg = idx & 7;
        uint32_t so = swz((uint32_t)row, (uint32_t)(seg * 16));
        int gm = bm + row;
        bool am = active && (gm < M);
        size_t aoff = am ? ((size_t)gm * K + k0 + seg * 8) : 0;
        cp_async16(sb + SB_AH + so, Ah + aoff, am);
        cp_async16(sb + SB_AL + so, Al + aoff, am);
    }
    // B: 64 rows x 8 segs = 512 slots (2 iters)
#pragma unroll
    for (int t = 0; t < 2; t++) {
        int idx = t * 256 + tid;
        int row = idx >> 3, seg = idx & 7;
        uint32_t so = swz((uint32_t)row, (uint32_t)(seg * 16));
        size_t boff = (size_t)(bn + row) * K + k0 + seg * 8;
        cp_async16(sb + SB_BH + so, Bh + boff, active);
        cp_async16(sb + SB_BL + so, Bl + boff, active);
    }
}

__global__ void __launch_bounds__(256, 2)
mma_gemm_kernel(const __nv_bfloat16* __restrict__ Ah, const __nv_bfloat16* __restrict__ Al,
                const __nv_bfloat16* __restrict__ Bh, const __nv_bfloat16* __restrict__ Bl,
                const float* __restrict__ bias1, const float* __restrict__ bias2,
                float* __restrict__ C, float* __restrict__ C2,
                __nv_bfloat16* __restrict__ Chi, __nv_bfloat16* __restrict__ Clo,
                int M, int N1, int K, int relu)
{
    const uint32_t s0 = smem_to_u32(dyn_smem);
    const int tid  = threadIdx.x;
    const int wid  = tid >> 5;
    const int lane = tid & 31;
    const int wm   = wid & 3;    // 4 warps in m
    const int wn   = wid >> 2;   // 2 warps in n
    const int bm = blockIdx.y * 128;
    const int bn = blockIdx.x * 64;
    const int Ntot = gridDim.x * 64;

    float acc[2][4][4];
#pragma unroll
    for (int i = 0; i < 2; i++)
#pragma unroll
        for (int j = 0; j < 4; j++)
#pragma unroll
            for (int c = 0; c < 4; c++) acc[i][j][c] = 0.f;

    const int nch = K >> 6;

    // prologue: fill 2 stages
#pragma unroll
    for (int s = 0; s < 2; s++) {
        gemm_issue_stage(s0 + s * STG_BYTES, Ah, Al, Bh, Bl, bm, bn, s << 6, M, K, tid, s < nch);
        CP_COMMIT();
    }

    for (int ch = 0; ch < nch; ch++) {
        CP_WAIT1();
        __syncthreads();
        const uint32_t sb = s0 + (ch & 1) * STG_BYTES;
        const uint32_t sAH = sb + SB_AH, sAL = sb + SB_AL;
        const uint32_t sBH = sb + SB_BH, sBL = sb + SB_BL;

#pragma unroll
        for (int ks = 0; ks < 4; ks++) {
            uint32_t a_h[2][4], a_l[2][4];
            {
                uint32_t rA = (uint32_t)(wm * 32 + (lane & 15));
                uint32_t kbA = (uint32_t)(ks * 32 + ((lane >> 4) << 4));
#pragma unroll
                for (int mt = 0; mt < 2; mt++) {
                    uint32_t off = swz(rA + mt * 16, kbA);
                    LDSM_X4(a_h[mt], sAH + off);
                    LDSM_X4(a_l[mt], sAL + off);
                }
            }
            uint32_t b_h[4][2], b_l[4][2];
            {
                uint32_t rB = (uint32_t)((lane & 7) + ((lane >> 4) << 3));
                uint32_t kbB = (uint32_t)(ks * 32 + (((lane >> 3) & 1) << 4));
#pragma unroll
                for (int np = 0; np < 2; np++) {
                    uint32_t row = (uint32_t)(wn * 32 + np * 16) + rB;
                    uint32_t off = swz(row, kbB);
                    uint32_t r4[4];
                    LDSM_X4(r4, sBH + off);
                    b_h[np * 2][0] = r4[0]; b_h[np * 2][1] = r4[1];
                    b_h[np * 2 + 1][0] = r4[2]; b_h[np * 2 + 1][1] = r4[3];
                    LDSM_X4(r4, sBL + off);
                    b_l[np * 2][0] = r4[0]; b_l[np * 2][1] = r4[1];
                    b_l[np * 2 + 1][0] = r4[2]; b_l[np * 2 + 1][1] = r4[3];
                }
            }
#pragma unroll
            for (int mt = 0; mt < 2; mt++)
#pragma unroll
                for (int nt = 0; nt < 4; nt++) {
                    MMA_BF16(acc[mt][nt], a_h[mt], b_h[nt]);
                    MMA_BF16(acc[mt][nt], a_l[mt], b_h[nt]);
                    MMA_BF16(acc[mt][nt], a_h[mt], b_l[nt]);
                }
        }
        __syncthreads();
        int nxt = ch + 2;
        gemm_issue_stage(s0 + (nxt & 1) * STG_BYTES, Ah, Al, Bh, Bl,
                         bm, bn, nxt << 6, M, K, tid, nxt < nch);
        CP_COMMIT();
    }

    // epilogue
    const int mrow0 = bm + wm * 32;
    const int ncol0 = bn + wn * 32;
#pragma unroll
    for (int mt = 0; mt < 2; mt++) {
        int r0 = mrow0 + mt * 16 + (lane >> 2);
        int r1 = r0 + 8;
#pragma unroll
        for (int nt = 0; nt < 4; nt++) {
            int n = ncol0 + nt * 8 + (lane & 3) * 2;
            float* dst; int stride; int nc;
            float bi0, bi1;
            if (C2 && n >= N1) {
                nc = n - N1; dst = C2; stride = Ntot - N1;
                bi0 = __ldg(&bias2[nc]); bi1 = __ldg(&bias2[nc + 1]);
            } else {
                nc = n; dst = C; stride = N1;
                bi0 = __ldg(&bias1[nc]); bi1 = __ldg(&bias1[nc + 1]);
            }
            float v00 = acc[mt][nt][0] + bi0, v01 = acc[mt][nt][1] + bi1;
            float v10 = acc[mt][nt][2] + bi0, v11 = acc[mt][nt][3] + bi1;
            if (relu) {
                v00 = fmaxf(v00, 0.f); v01 = fmaxf(v01, 0.f);
                v10 = fmaxf(v10, 0.f); v11 = fmaxf(v11, 0.f);
            }
            if (dst) {
                if (r0 < M) *(float2*)(dst + (size_t)r0 * stride + nc) = make_float2(v00, v01);
                if (r1 < M) *(float2*)(dst + (size_t)r1 * stride + nc) = make_float2(v10, v11);
            } else {
                __nv_bfloat16 h0, l0, h1, l1;
                if (r0 < M) {
                    split_bf16(v00, h0, l0); split_bf16(v01, h1, l1);
                    *(__nv_bfloat162*)(Chi + (size_t)r0 * Ntot + n) = __nv_bfloat162(h0, h1);
                    *(__nv_bfloat162*)(Clo + (size_t)r0 * Ntot + n) = __nv_bfloat162(l0, l1);
                }
                if (r1 < M) {
                    split_bf16(v10, h0, l0); split_bf16(v11, h1, l1);
                    *(__nv_bfloat162*)(Chi + (size_t)r1 * Ntot + n) = __nv_bfloat162(h0, h1);
                    *(__nv_bfloat162*)(Clo + (size_t)r1 * Ntot + n) = __nv_bfloat162(l0, l1);
                }
            }
        }
    }
}

// ---------------- build q and v_in (+ bf16 splits) ----------------
__global__ void build_qv_kernel(const float* __restrict__ src,
                                const float* __restrict__ pos,
                                const float* __restrict__ sel_vt)
{
    size_t idx = (size_t)blockIdx.x * blockDim.x + threadIdx.x;
    size_t total = (size_t)ROWS * DM;
    if (idx >= total) return;
    size_t row = idx / DM;
    int d = (int)(idx % DM);
    int n = (int)(row / LQ);
    int r = (int)(row % LQ);
    float qv, vv;
    if (r < L_SP) {
        size_t si = ((size_t)n * L_SP + r) * DM + d;
        float s = src[si];
        qv = s + pos[si];
        vv = s;
    } else {
        size_t si = ((size_t)n * N_VT + (r - L_SP)) * DM + d;
        float s = sel_vt[si];
        qv = s; vv = s;
    }
    g_v[idx] = vv;
    __nv_bfloat16 h, l;
    split_bf16(qv, h, l); g_qh[idx] = h; g_ql[idx] = l;
    split_bf16(vv, h, l); g_vh[idx] = h; g_vl[idx] = l;
}

// ---------------- all weight splits in ONE kernel ----------------
__global__ void conv_all_kernel(const float* __restrict__ Wv, const float* __restrict__ Wo,
                                const float* __restrict__ Wa, const float* __restrict__ Wout,
                                const float* __restrict__ W1, const float* __restrict__ W2)
{
    int i = blockIdx.x * blockDim.x + threadIdx.x;
    if (i >= WTOT) return;
    float x;
    if      (i < WOFF_O)   x = Wv  [i];
    else if (i < WOFF_A)   x = Wo  [i - WOFF_O];
    else if (i < WOFF_OUT) x = Wa  [i - WOFF_A];
    else if (i < WOFF_1)   x = Wout[i - WOFF_OUT];
    else if (i < WOFF_2)   x = W1  [i - WOFF_1];
    else                   x = W2  [i - WOFF_2];
    __nv_bfloat16 h, l;
    split_bf16(x, h, l);
    g_wbh[i] = h; g_wbl[i] = l;
}

// ---------------- softmax over 16 points per (row, head) ----------------
__global__ void softmax16_kernel()
{
    int t = blockIdx.x * blockDim.x + threadIdx.x;
    if (t >= ROWS * NH) return;
    size_t base = (size_t)(t >> 3) * 128 + (t & 7) * 16;
    float v[16];
    float mx = -1e30f;
#pragma unroll
    for (int i = 0; i < 16; i++) { v[i] = g_attn[base + i]; mx = fmaxf(mx, v[i]); }
    float s = 0.f;
#pragma unroll
    for (int i = 0; i < 16; i++) { v[i] = __expf(v[i] - mx); s += v[i]; }
    float inv = 1.f / s;
#pragma unroll
    for (int i = 0; i < 16; i++) g_attn[base + i] = v[i] * inv;
}

// ---------------- deformable sampling -> bf16 hi/lo ----------------
__global__ void sample_kernel(const float* __restrict__ ref)
{
    const int row = blockIdx.x;
    const int m   = threadIdx.x >> 5;
    const int d   = threadIdx.x & 31;
    const int n   = row / LQ;

    const float* refp = ref + (size_t)row * (NLEV * 2);
    const float* offp = g_off + (size_t)row * DM + m * (NLEV * NPTS * 2);
    const float* attp = g_attn + (size_t)row * 128 + m * 16;
    const float* valn = g_val + (size_t)n * LQ * DM;

    float acc = 0.f;
#pragma unroll
    for (int l = 0; l < NLEV; l++) {
        const int H = c_H[l], W = c_W[l], st = c_start[l];
        const float rx = refp[l * 2 + 0];
        const float ry = refp[l * 2 + 1];
#pragma unroll
        for (int p = 0; p < NPTS; p++) {
            const float ox = offp[(l * NPTS + p) * 2 + 0];
            const float oy = offp[(l * NPTS + p) * 2 + 1];
            const float a  = attp[l * NPTS + p];
            const float x = rx * W + ox - 0.5f;
            const float y = ry * H + oy - 0.5f;
            const float x0f = floorf(x), y0f = floorf(y);
            const float wx = x - x0f, wy = y - y0f;
            const int x0 = (int)x0f, y0 = (int)y0f;
            const int x1 = x0 + 1,   y1 = y0 + 1;
            const bool vx0 = (x0 >= 0) & (x0 < W);
            const bool vx1 = (x1 >= 0) & (x1 < W);
            const bool vy0 = (y0 >= 0) & (y0 < H);
            const bool vy1 = (y1 >= 0) & (y1 < H);
            const float w00 = (1.f - wx) * (1.f - wy);
            const float w10 = wx * (1.f - wy);
            const float w01 = (1.f - wx) * wy;
            const float w11 = wx * wy;
            if (vx0 & vy0) acc += a * w00 * valn[((size_t)(st + y0 * W + x0)) * DM + m * DH + d];
            if (vx1 & vy0) acc += a * w10 * valn[((size_t)(st + y0 * W + x1)) * DM + m * DH + d];
            if (vx0 & vy1) acc += a * w01 * valn[((size_t)(st + y1 * W + x0)) * DM + m * DH + d];
            if (vx1 & vy1) acc += a * w11 * valn[((size_t)(st + y1 * W + x1)) * DM + m * DH + d];
        }
    }
    __nv_bfloat16 h, l;
    split_bf16(acc, h, l);
    size_t oi = (size_t)row * DM + m * DH + d;
    g_sh[oi] = h; g_sl[oi] = l;
}

// ---------------- residual + LayerNorm (+ optional bf16 split out) ----------------
__global__ void resid_ln_kernel(const float* __restrict__ a,
                                const float* __restrict__ b,
                                const float* __restrict__ g,
                                const float* __restrict__ beta,
                                float* __restrict__ out,
                                __nv_bfloat16* __restrict__ outH,
                                __nv_bfloat16* __restrict__ outL)
{
    __shared__ float red[64];
    const int row = blockIdx.x;
    const int t = threadIdx.x;
    size_t base = (size_t)row * DM;
    float x = a[base + t] + b[base + t];

    float s = x;
#pragma unroll
    for (int o = 16; o > 0; o >>= 1) s += __shfl_xor_sync(0xffffffffu, s, o);
    if ((t & 31) == 0) red[t >> 5] = s;
    __syncthreads();
    if (t < 8) {
        float v = red[t];
#pragma unroll
        for (int o = 4; o > 0; o >>= 1) v += __shfl_xor_sync(0xffu, v, o);
        if (t == 0) red[32] = v;
    }
    __syncthreads();
    float mean = red[32] * (1.f / DM);

    float xc = x - mean;
    float sq = xc * xc;
#pragma unroll
    for (int o = 16; o > 0; o >>= 1) sq += __shfl_xor_sync(0xffffffffu, sq, o);
    if ((t & 31) == 0) red[t >> 5] = sq;
    __syncthreads();
    if (t < 8) {
        float v = red[t];
#pragma unroll
        for (int o = 4; o > 0; o >>= 1) v += __shfl_xor_sync(0xffu, v, o);
        if (t == 0) red[33] = v;
    }
    __syncthreads();
    float var = red[33] * (1.f / DM);
    float inv = rsqrtf(var + EPSLN);
    float y = g[t] * xc * inv + beta[t];
    out[base + t] = y;
    if (outH) {
        __nv_bfloat16 h, l;
        split_bf16(y, h, l);
        outH[base + t] = h; outL[base + t] = l;
    }
}

// ---------------- assemble final output ----------------
__global__ void write_out_kernel(const float* __restrict__ all_vt, float* __restrict__ out)
{
    const size_t P1 = (size_t)NB * L_SP * DM;
    const size_t P2 = (size_t)NB * 75 * N_VT * DM;
    const size_t P3 = (size_t)NB * N_VT * DM;
    size_t idx = (size_t)blockIdx.x * blockDim.x + threadIdx.x;
    if (idx < P1) {
        size_t row = idx / DM; int d = (int)(idx % DM);
        int n = (int)(row / L_SP), r = (int)(row % L_SP);
        out[idx] = g_x[((size_t)n * LQ + r) * DM + d];
    } else if (idx < P1 + P2) {
        out[idx] = all_vt[idx - P1];
    } else if (idx < P1 + P2 + P3) {
        size_t k = idx - P1 - P2;
        size_t row = k / DM; int d = (int)(k % DM);
        int n = (int)(row / N_VT), r = (int)(row % N_VT);
        out[idx] = g_x[((size_t)n * LQ + L_SP + r) * DM + d];
    }
}

// ---------------- launch ----------------
extern "C" void kernel_launch(void* const* d_in, const int* in_sizes, int n_in,
                              void* d_out, int out_size)
{
    const float* src     = (const float*)d_in[0];
    const float* pos     = (const float*)d_in[1];
    const float* refpts  = (const float*)d_in[2];
    const float* all_vt  = (const float*)d_in[6];
    const float* sel_vt  = (const float*)d_in[7];
    const float* W_value = (const float*)d_in[8];
    const float* b_value = (const float*)d_in[9];
    const float* W_off   = (const float*)d_in[10];
    const float* b_off   = (const float*)d_in[11];
    const float* W_attn  = (const float*)d_in[12];
    const float* b_attn  = (const float*)d_in[13];
    const float* W_out   = (const float*)d_in[14];
    const float* b_out   = (const float*)d_in[15];
    const float* g1      = (const float*)d_in[16];
    const float* beta1   = (const float*)d_in[17];
    const float* W1      = (const float*)d_in[18];
    const float* bf1     = (const float*)d_in[19];
    const float* W2      = (const float*)d_in[20];
    const float* bf2     = (const float*)d_in[21];
    const float* g2      = (const float*)d_in[22];
    const float* beta2   = (const float*)d_in[23];
    float* out = (float*)d_out;

    float* p_v;    cudaGetSymbolAddress((void**)&p_v,    g_v);
    float* p_val;  cudaGetSymbolAddress((void**)&p_val,  g_val);
    float* p_off;  cudaGetSymbolAddress((void**)&p_off,  g_off);
    float* p_attn; cudaGetSymbolAddress((void**)&p_attn, g_attn);
    float* p_tmp;  cudaGetSymbolAddress((void**)&p_tmp,  g_tmp);
    float* p_x;    cudaGetSymbolAddress((void**)&p_x,    g_x);
    __nv_bfloat16 *p_qh, *p_ql, *p_vh, *p_vl, *p_sh, *p_sl, *p_xh, *p_xl, *p_h1h, *p_h1l, *p_wbh, *p_wbl;
    cudaGetSymbolAddress((void**)&p_qh,  g_qh);
    cudaGetSymbolAddress((void**)&p_ql,  g_ql);
    cudaGetSymbolAddress((void**)&p_vh,  g_vh);
    cudaGetSymbolAddress((void**)&p_vl,  g_vl);
    cudaGetSymbolAddress((void**)&p_sh,  g_sh);
    cudaGetSymbolAddress((void**)&p_sl,  g_sl);
    cudaGetSymbolAddress((void**)&p_xh,  g_xh);
    cudaGetSymbolAddress((void**)&p_xl,  g_xl);
    cudaGetSymbolAddress((void**)&p_h1h, g_h1h);
    cudaGetSymbolAddress((void**)&p_h1l, g_h1l);
    cudaGetSymbolAddress((void**)&p_wbh, g_wbh);
    cudaGetSymbolAddress((void**)&p_wbl, g_wbl);

    static int smem_set = 0;
    if (!smem_set) {
        cudaFuncSetAttribute(mma_gemm_kernel, cudaFuncAttributeMaxDynamicSharedMemorySize, GSM_TOTAL);
        smem_set = 1;
    }

    const int M = ROWS;
    const int MT = (M + 127) / 128;   // 171

    // 1. build q, v (with bf16 splits)
    {
        size_t total = (size_t)ROWS * DM;
        build_qv_kernel<<<(unsigned)((total + 255) / 256), 256>>>(src, pos, sel_vt);
    }
    // 2. weight splits (single kernel)
    conv_all_kernel<<<(WTOT + 255) / 256, 256>>>(W_value, W_off, W_attn, W_out, W1, W2);

    // 3. value projection (N=256 -> x=4)
    mma_gemm_kernel<<<dim3(4, MT), 256, GSM_TOTAL>>>(p_vh, p_vl, p_wbh + WOFF_V, p_wbl + WOFF_V,
        b_value, nullptr, p_val, nullptr, nullptr, nullptr, M, DM, DM, 0);
    // 4. fused offsets+attn: B = [Wo; Wa], N=384 -> x=6; cols<256 -> g_off, cols>=256 -> g_attn
    mma_gemm_kernel<<<dim3(6, MT), 256, GSM_TOTAL>>>(p_qh, p_ql, p_wbh + WOFF_O, p_wbl + WOFF_O,
        b_off, b_attn, p_off, p_attn, nullptr, nullptr, M, DM, DM, 0);
    // 5. softmax
    softmax16_kernel<<<(ROWS * NH + 255) / 256, 256>>>();
    // 6. deformable sampling -> bf16 splits
    sample_kernel<<<ROWS, 256>>>(refpts);
    // 7. output projection -> g_tmp
    mma_gemm_kernel<<<dim3(4, MT), 256, GSM_TOTAL>>>(p_sh, p_sl, p_wbh + WOFF_OUT, p_wbl + WOFF_OUT,
        b_out, nullptr, p_tmp, nullptr, nullptr, nullptr, M, DM, DM, 0);
    // 8. x = LN(v + src2) (+ bf16 splits)
    resid_ln_kernel<<<ROWS, 256>>>(p_v, p_tmp, g1, beta1, p_x, p_xh, p_xl);
    // 9. h1 = relu(x @ W1^T + bf1) -> bf16 splits directly (N=1024 -> x=16)
    mma_gemm_kernel<<<dim3(16, MT), 256, GSM_TOTAL>>>(p_xh, p_xl, p_wbh + WOFF_1, p_wbl + WOFF_1,
        bf1, nullptr, nullptr, nullptr, p_h1h, p_h1l, M, DF, DM, 1);
    // 10. h = h1 @ W2^T + bf2 -> g_tmp (K=1024)
    mma_gemm_kernel<<<dim3(4, MT), 256, GSM_TOTAL>>>(p_h1h, p_h1l, p_wbh + WOFF_2, p_wbl + WOFF_2,
        bf2, nullptr, p_tmp, nullptr, nullptr, nullptr, M, DM, DF, 0);
    // 11. x = LN(x + h)
    resid_ln_kernel<<<ROWS, 256>>>(p_x, p_tmp, g2, beta2, p_x, nullptr, nullptr);
    // 12. assemble outputs
    {
        size_t total = (size_t)NB * (L_SP + 75 * N_VT + N_VT) * DM;
        write_out_kernel<<<(unsigned)((total + 255) / 256), 256>>>(all_vt, out);
    }
}

// round 7
// speedup vs baseline: 3.1797x; 1.1103x over previous
#include <cuda_runtime.h>
#include <cuda_fp16.h>
#include <math.h>
#include <cstdint>

// ---------------- problem constants ----------------
#define NB     4
#define L_SP   5440
#define N_VT   8
#define LQ     (L_SP + N_VT)      // 5448
#define DM     256
#define DF     1024
#define NH     8
#define DH     32
#define NLEV   4
#define NPTS   4
#define ROWS   (NB * LQ)          // 21792
#define EPSLN  1e-5f

__device__ __constant__ int c_H[NLEV]     = {64, 32, 16, 8};
__device__ __constant__ int c_W[NLEV]     = {64, 32, 16, 8};
__device__ __constant__ int c_start[NLEV] = {0, 4096, 5120, 5376};

// ---------------- scratch (device globals; no allocs) ----------------
static __device__ float g_v   [ (size_t)ROWS * DM ];   // v_in fp32 (residual 1)
static __device__ float g_off [ (size_t)ROWS * DM ];
static __device__ float g_attn[ (size_t)ROWS * 128 ];
static __device__ float g_tmp [ (size_t)ROWS * DM ];
static __device__ float g_x   [ (size_t)ROWS * DM ];

static __device__ __half g_valh[ (size_t)ROWS * DM ];  // value projection, fp16 (sampling source)
static __device__ __half g_qh [ (size_t)ROWS * DM ];
static __device__ __half g_ql [ (size_t)ROWS * DM ];
static __device__ __half g_vh [ (size_t)ROWS * DM ];
static __device__ __half g_vl [ (size_t)ROWS * DM ];
static __device__ __half g_sh [ (size_t)ROWS * DM ];
static __device__ __half g_sl [ (size_t)ROWS * DM ];
static __device__ __half g_xh [ (size_t)ROWS * DM ];
static __device__ __half g_xl [ (size_t)ROWS * DM ];
static __device__ __half g_h1h[ (size_t)ROWS * DF ];
static __device__ __half g_h1l[ (size_t)ROWS * DF ];

// weights (concatenated, fp16 hi only): Wv | Wo | Wa | Wout | W1 | W2
#define WOFF_V    0
#define WOFF_O    65536
#define WOFF_A    131072
#define WOFF_OUT  163840
#define WOFF_1    229376
#define WOFF_2    491520
#define WTOT      753664
static __device__ __half g_wh[WTOT];

// ---------------- helpers ----------------
__device__ __forceinline__ uint32_t smem_to_u32(const void* p) {
    uint32_t a;
    asm("{ .reg .u64 t; cvta.to.shared.u64 t, %1; cvt.u32.u64 %0, t; }" : "=r"(a) : "l"(p));
    return a;
}

#define LDSM_X4(r, addr) \
    asm volatile("ldmatrix.sync.aligned.m8n8.x4.shared.b16 {%0,%1,%2,%3}, [%4];" \
        : "=r"((r)[0]), "=r"((r)[1]), "=r"((r)[2]), "=r"((r)[3]) : "r"(addr))

#define MMA_F16(d, a, b) \
    asm volatile("mma.sync.aligned.m16n8k16.row.col.f32.f16.f16.f32 " \
        "{%0,%1,%2,%3}, {%4,%5,%6,%7}, {%8,%9}, {%0,%1,%2,%3};" \
        : "+f"((d)[0]), "+f"((d)[1]), "+f"((d)[2]), "+f"((d)[3]) \
        : "r"((a)[0]), "r"((a)[1]), "r"((a)[2]), "r"((a)[3]), \
          "r"((b)[0]), "r"((b)[1]))

__device__ __forceinline__ void cp_async16(uint32_t dst, const void* src, bool pred) {
    int sz = pred ? 16 : 0;
    asm volatile("cp.async.cg.shared.global [%0], [%1], 16, %2;"
        :: "r"(dst), "l"(src), "r"(sz) : "memory");
}
#define CP_COMMIT() asm volatile("cp.async.commit_group;" ::: "memory")
#define CP_WAIT1()  asm volatile("cp.async.wait_group 1;" ::: "memory")

// swizzled byte offset within rows of 128 bytes
__device__ __forceinline__ uint32_t swz(uint32_t row, uint32_t kb) {
    return row * 128u + (kb ^ ((row & 7u) << 4));
}

__device__ __forceinline__ void split_f16(float x, __half& h, __half& l) {
    h = __float2half(x);
    l = __float2half(x - __half2float(h));
}

// ---------------- pipelined warp-MMA 2-term fp16 GEMM ----------------
// C = (Ah+Al) @ Bh^T + bias. CTA tile 128x64, BK=64, 256 threads (8 warps, 4m x 2n),
// warp tile 32x32. 2-stage cp.async pipeline; stage = 40KB (AH 16K, AL 16K, BH 8K).
// 2 CTAs/SM.
#define STG_BYTES 40960
#define SB_AH 0
#define SB_AL 16384
#define SB_BH 32768
#define GSM_TOTAL (2 * STG_BYTES)   // 81920

extern __shared__ char dyn_smem[];

__device__ __forceinline__ void gemm_issue_stage(
    uint32_t sb, const __half* Ah, const __half* Al, const __half* Bh,
    int bm, int bn, int k0, int M, int K, int tid, bool active)
{
    // A: 128 rows x 8 segs of 16B = 1024 slots (4 iters over 256 threads)
#pragma unroll
    for (int t = 0; t < 4; t++) {
        int idx = t * 256 + tid;
        int row = idx >> 3, seg = idx & 7;
        uint32_t so = swz((uint32_t)row, (uint32_t)(seg * 16));
        int gm = bm + row;
        bool am = active && (gm < M);
        size_t aoff = am ? ((size_t)gm * K + k0 + seg * 8) : 0;
        cp_async16(sb + SB_AH + so, Ah + aoff, am);
        cp_async16(sb + SB_AL + so, Al + aoff, am);
    }
    // B: 64 rows x 8 segs = 512 slots (2 iters)
#pragma unroll
    for (int t = 0; t < 2; t++) {
        int idx = t * 256 + tid;
        int row = idx >> 3, seg = idx & 7;
        uint32_t so = swz((uint32_t)row, (uint32_t)(seg * 16));
        size_t boff = (size_t)(bn + row) * K + k0 + seg * 8;
        cp_async16(sb + SB_BH + so, Bh + boff, active);
    }
}

__global__ void __launch_bounds__(256, 2)
mma_gemm_kernel(const __half* __restrict__ Ah, const __half* __restrict__ Al,
                const __half* __restrict__ Bh,
                const float* __restrict__ bias1, const float* __restrict__ bias2,
                float* __restrict__ C, float* __restrict__ C2,
                __half* __restrict__ Chi, __half* __restrict__ Clo,
                int M, int N1, int K, int relu)
{
    const uint32_t s0 = smem_to_u32(dyn_smem);
    const int tid  = threadIdx.x;
    const int wid  = tid >> 5;
    const int lane = tid & 31;
    const int wm   = wid & 3;
    const int wn   = wid >> 2;
    const int bm = blockIdx.y * 128;
    const int bn = blockIdx.x * 64;
    const int Ntot = gridDim.x * 64;

    float acc[2][4][4];
#pragma unroll
    for (int i = 0; i < 2; i++)
#pragma unroll
        for (int j = 0; j < 4; j++)
#pragma unroll
            for (int c = 0; c < 4; c++) acc[i][j][c] = 0.f;

    const int nch = K >> 6;

#pragma unroll
    for (int s = 0; s < 2; s++) {
        gemm_issue_stage(s0 + s * STG_BYTES, Ah, Al, Bh, bm, bn, s << 6, M, K, tid, s < nch);
        CP_COMMIT();
    }

    for (int ch = 0; ch < nch; ch++) {
        CP_WAIT1();
        __syncthreads();
        const uint32_t sb = s0 + (ch & 1) * STG_BYTES;
        const uint32_t sAH = sb + SB_AH, sAL = sb + SB_AL, sBH = sb + SB_BH;

#pragma unroll
        for (int ks = 0; ks < 4; ks++) {
            uint32_t a_h[2][4], a_l[2][4];
            {
                uint32_t rA = (uint32_t)(wm * 32 + (lane & 15));
                uint32_t kbA = (uint32_t)(ks * 32 + ((lane >> 4) << 4));
#pragma unroll
                for (int mt = 0; mt < 2; mt++) {
                    uint32_t off = swz(rA + mt * 16, kbA);
                    LDSM_X4(a_h[mt], sAH + off);
                    LDSM_X4(a_l[mt], sAL + off);
                }
            }
            uint32_t b_h[4][2];
            {
                uint32_t rB = (uint32_t)((lane & 7) + ((lane >> 4) << 3));
                uint32_t kbB = (uint32_t)(ks * 32 + (((lane >> 3) & 1) << 4));
#pragma unroll
                for (int np = 0; np < 2; np++) {
                    uint32_t row = (uint32_t)(wn * 32 + np * 16) + rB;
                    uint32_t off = swz(row, kbB);
                    uint32_t r4[4];
                    LDSM_X4(r4, sBH + off);
                    b_h[np * 2][0] = r4[0]; b_h[np * 2][1] = r4[1];
                    b_h[np * 2 + 1][0] = r4[2]; b_h[np * 2 + 1][1] = r4[3];
                }
            }
#pragma unroll
            for (int mt = 0; mt < 2; mt++)
#pragma unroll
                for (int nt = 0; nt < 4; nt++) {
                    MMA_F16(acc[mt][nt], a_h[mt], b_h[nt]);
                    MMA_F16(acc[mt][nt], a_l[mt], b_h[nt]);
                }
        }
        __syncthreads();
        int nxt = ch + 2;
        gemm_issue_stage(s0 + (nxt & 1) * STG_BYTES, Ah, Al, Bh,
                         bm, bn, nxt << 6, M, K, tid, nxt < nch);
        CP_COMMIT();
    }

    // epilogue
    const int mrow0 = bm + wm * 32;
    const int ncol0 = bn + wn * 32;
#pragma unroll
    for (int mt = 0; mt < 2; mt++) {
        int r0 = mrow0 + mt * 16 + (lane >> 2);
        int r1 = r0 + 8;
#pragma unroll
        for (int nt = 0; nt < 4; nt++) {
            int n = ncol0 + nt * 8 + (lane & 3) * 2;
            float* dst; int stride; int nc;
            float bi0, bi1;
            if (C2 && n >= N1) {
                nc = n - N1; dst = C2; stride = Ntot - N1;
                bi0 = __ldg(&bias2[nc]); bi1 = __ldg(&bias2[nc + 1]);
            } else {
                nc = n; dst = C; stride = N1;
                bi0 = __ldg(&bias1[nc]); bi1 = __ldg(&bias1[nc + 1]);
            }
            float v00 = acc[mt][nt][0] + bi0, v01 = acc[mt][nt][1] + bi1;
            float v10 = acc[mt][nt][2] + bi0, v11 = acc[mt][nt][3] + bi1;
            if (relu) {
                v00 = fmaxf(v00, 0.f); v01 = fmaxf(v01, 0.f);
                v10 = fmaxf(v10, 0.f); v11 = fmaxf(v11, 0.f);
            }
            if (C) {
                if (r0 < M) *(float2*)(dst + (size_t)r0 * stride + nc) = make_float2(v00, v01);
                if (r1 < M) *(float2*)(dst + (size_t)r1 * stride + nc) = make_float2(v10, v11);
            } else if (Clo) {
                __half h0, l0, h1, l1;
                if (r0 < M) {
                    split_f16(v00, h0, l0); split_f16(v01, h1, l1);
                    *(__half2*)(Chi + (size_t)r0 * Ntot + n) = __halves2half2(h0, h1);
                    *(__half2*)(Clo + (size_t)r0 * Ntot + n) = __halves2half2(l0, l1);
                }
                if (r1 < M) {
                    split_f16(v10, h0, l0); split_f16(v11, h1, l1);
                    *(__half2*)(Chi + (size_t)r1 * Ntot + n) = __halves2half2(h0, h1);
                    *(__half2*)(Clo + (size_t)r1 * Ntot + n) = __halves2half2(l0, l1);
                }
            } else {
                if (r0 < M)
                    *(__half2*)(Chi + (size_t)r0 * Ntot + n) =
                        __halves2half2(__float2half(v00), __float2half(v01));
                if (r1 < M)
                    *(__half2*)(Chi + (size_t)r1 * Ntot + n) =
                        __halves2half2(__float2half(v10), __float2half(v11));
            }
        }
    }
}

// ---------------- build q and v_in (+ fp16 splits) ----------------
__global__ void build_qv_kernel(const float* __restrict__ src,
                                const float* __restrict__ pos,
                                const float* __restrict__ sel_vt)
{
    size_t idx = (size_t)blockIdx.x * blockDim.x + threadIdx.x;
    size_t total = (size_t)ROWS * DM;
    if (idx >= total) return;
    size_t row = idx / DM;
    int d = (int)(idx % DM);
    int n = (int)(row / LQ);
    int r = (int)(row % LQ);
    float qv, vv;
    if (r < L_SP) {
        size_t si = ((size_t)n * L_SP + r) * DM + d;
        float s = src[si];
        qv = s + pos[si];
        vv = s;
    } else {
        size_t si = ((size_t)n * N_VT + (r - L_SP)) * DM + d;
        float s = sel_vt[si];
        qv = s; vv = s;
    }
    g_v[idx] = vv;
    __half h, l;
    split_f16(qv, h, l); g_qh[idx] = h; g_ql[idx] = l;
    split_f16(vv, h, l); g_vh[idx] = h; g_vl[idx] = l;
}

// ---------------- all weight conversions in ONE kernel (fp16 round) ----------------
__global__ void conv_all_kernel(const float* __restrict__ Wv, const float* __restrict__ Wo,
                                const float* __restrict__ Wa, const float* __restrict__ Wout,
                                const float* __restrict__ W1, const float* __restrict__ W2)
{
    int i = blockIdx.x * blockDim.x + threadIdx.x;
    if (i >= WTOT) return;
    float x;
    if      (i < WOFF_O)   x = Wv  [i];
    else if (i < WOFF_A)   x = Wo  [i - WOFF_O];
    else if (i < WOFF_OUT) x = Wa  [i - WOFF_A];
    else if (i < WOFF_1)   x = Wout[i - WOFF_OUT];
    else if (i < WOFF_2)   x = W1  [i - WOFF_1];
    else                   x = W2  [i - WOFF_2];
    g_wh[i] = __float2half(x);
}

// ---------------- softmax over 16 points per (row, head) ----------------
__global__ void softmax16_kernel()
{
    int t = blockIdx.x * blockDim.x + threadIdx.x;
    if (t >= ROWS * NH) return;
    size_t base = (size_t)(t >> 3) * 128 + (t & 7) * 16;
    float v[16];
    float mx = -1e30f;
#pragma unroll
    for (int i = 0; i < 16; i++) { v[i] = g_attn[base + i]; mx = fmaxf(mx, v[i]); }
    float s = 0.f;
#pragma unroll
    for (int i = 0; i < 16; i++) { v[i] = __expf(v[i] - mx); s += v[i]; }
    float inv = 1.f / s;
#pragma unroll
    for (int i = 0; i < 16; i++) g_attn[base + i] = v[i] * inv;
}

// ---------------- deformable sampling (fp16 value) -> fp16 hi/lo ----------------
__global__ void sample_kernel(const float* __restrict__ ref)
{
    const int row = blockIdx.x;
    const int m   = threadIdx.x >> 5;
    const int d   = threadIdx.x & 31;
    const int n   = row / LQ;

    const float* refp = ref + (size_t)row * (NLEV * 2);
    const float* offp = g_off + (size_t)row * DM + m * (NLEV * NPTS * 2);
    const float* attp = g_attn + (size_t)row * 128 + m * 16;
    const __half* valn = g_valh + (size_t)n * LQ * DM;

    float acc = 0.f;
#pragma unroll
    for (int l = 0; l < NLEV; l++) {
        const int H = c_H[l], W = c_W[l], st = c_start[l];
        const float rx = refp[l * 2 + 0];
        const float ry = refp[l * 2 + 1];
#pragma unroll
        for (int p = 0; p < NPTS; p++) {
            const float ox = offp[(l * NPTS + p) * 2 + 0];
            const float oy = offp[(l * NPTS + p) * 2 + 1];
            const float a  = attp[l * NPTS + p];
            const float x = rx * W + ox - 0.5f;
            const float y = ry * H + oy - 0.5f;
            const float x0f = floorf(x), y0f = floorf(y);
            const float wx = x - x0f, wy = y - y0f;
            const int x0 = (int)x0f, y0 = (int)y0f;
            const int x1 = x0 + 1,   y1 = y0 + 1;
            const bool vx0 = (x0 >= 0) & (x0 < W);
            const bool vx1 = (x1 >= 0) & (x1 < W);
            const bool vy0 = (y0 >= 0) & (y0 < H);
            const bool vy1 = (y1 >= 0) & (y1 < H);
            const float w00 = (1.f - wx) * (1.f - wy);
            const float w10 = wx * (1.f - wy);
            const float w01 = (1.f - wx) * wy;
            const float w11 = wx * wy;
            if (vx0 & vy0) acc += a * w00 * __half2float(valn[((size_t)(st + y0 * W + x0)) * DM + m * DH + d]);
            if (vx1 & vy0) acc += a * w10 * __half2float(valn[((size_t)(st + y0 * W + x1)) * DM + m * DH + d]);
            if (vx0 & vy1) acc += a * w01 * __half2float(valn[((size_t)(st + y1 * W + x0)) * DM + m * DH + d]);
            if (vx1 & vy1) acc += a * w11 * __half2float(valn[((size_t)(st + y1 * W + x1)) * DM + m * DH + d]);
        }
    }
    __half h, l;
    split_f16(acc, h, l);
    size_t oi = (size_t)row * DM + m * DH + d;
    g_sh[oi] = h; g_sl[oi] = l;
}

// ---------------- residual + LayerNorm (+ optional fp16 split out) ----------------
__global__ void resid_ln_kernel(const float* __restrict__ a,
                                const float* __restrict__ b,
                                const float* __restrict__ g,
                                const float* __restrict__ beta,
                                float* __restrict__ out,
                                __half* __restrict__ outH,
                                __half* __restrict__ outL)
{
    __shared__ float red[64];
    const int row = blockIdx.x;
    const int t = threadIdx.x;
    size_t base = (size_t)row * DM;
    float x = a[base + t] + b[base + t];

    float s = x;
#pragma unroll
    for (int o = 16; o > 0; o >>= 1) s += __shfl_xor_sync(0xffffffffu, s, o);
    if ((t & 31) == 0) red[t >> 5] = s;
    __syncthreads();
    if (t < 8) {
        float v = red[t];
#pragma unroll
        for (int o = 4; o > 0; o >>= 1) v += __shfl_xor_sync(0xffu, v, o);
        if (t == 0) red[32] = v;
    }
    __syncthreads();
    float mean = red[32] * (1.f / DM);

    float xc = x - mean;
    float sq = xc * xc;
#pragma unroll
    for (int o = 16; o > 0; o >>= 1) sq += __shfl_xor_sync(0xffffffffu, sq, o);
    if ((t & 31) == 0) red[t >> 5] = sq;
    __syncthreads();
    if (t < 8) {
        float v = red[t];
#pragma unroll
        for (int o = 4; o > 0; o >>= 1) v += __shfl_xor_sync(0xffu, v, o);
        if (t == 0) red[33] = v;
    }
    __syncthreads();
    float var = red[33] * (1.f / DM);
    float inv = rsqrtf(var + EPSLN);
    float y = g[t] * xc * inv + beta[t];
    out[base + t] = y;
    if (outH) {
        __half h, l;
        split_f16(y, h, l);
        outH[base + t] = h; outL[base + t] = l;
    }
}

// ---------------- assemble final output ----------------
__global__ void write_out_kernel(const float* __restrict__ all_vt, float* __restrict__ out)
{
    const size_t P1 = (size_t)NB * L_SP * DM;
    const size_t P2 = (size_t)NB * 75 * N_VT * DM;
    const size_t P3 = (size_t)NB * N_VT * DM;
    size_t idx = (size_t)blockIdx.x * blockDim.x + threadIdx.x;
    if (idx < P1) {
        size_t row = idx / DM; int d = (int)(idx % DM);
        int n = (int)(row / L_SP), r = (int)(row % L_SP);
        out[idx] = g_x[((size_t)n * LQ + r) * DM + d];
    } else if (idx < P1 + P2) {
        out[idx] = all_vt[idx - P1];
    } else if (idx < P1 + P2 + P3) {
        size_t k = idx - P1 - P2;
        size_t row = k / DM; int d = (int)(k % DM);
        int n = (int)(row / N_VT), r = (int)(row % N_VT);
        out[idx] = g_x[((size_t)n * LQ + L_SP + r) * DM + d];
    }
}

// ---------------- launch ----------------
extern "C" void kernel_launch(void* const* d_in, const int* in_sizes, int n_in,
                              void* d_out, int out_size)
{
    const float* src     = (const float*)d_in[0];
    const float* pos     = (const float*)d_in[1];
    const float* refpts  = (const float*)d_in[2];
    const float* all_vt  = (const float*)d_in[6];
    const float* sel_vt  = (const float*)d_in[7];
    const float* W_value = (const float*)d_in[8];
    const float* b_value = (const float*)d_in[9];
    const float* W_off   = (const float*)d_in[10];
    const float* b_off   = (const float*)d_in[11];
    const float* W_attn  = (const float*)d_in[12];
    const float* b_attn  = (const float*)d_in[13];
    const float* W_out   = (const float*)d_in[14];
    const float* b_out   = (const float*)d_in[15];
    const float* g1      = (const float*)d_in[16];
    const float* beta1   = (const float*)d_in[17];
    const float* W1      = (const float*)d_in[18];
    const float* bf1     = (const float*)d_in[19];
    const float* W2      = (const float*)d_in[20];
    const float* bf2     = (const float*)d_in[21];
    const float* g2      = (const float*)d_in[22];
    const float* beta2   = (const float*)d_in[23];
    float* out = (float*)d_out;

    float* p_v;    cudaGetSymbolAddress((void**)&p_v,    g_v);
    float* p_off;  cudaGetSymbolAddress((void**)&p_off,  g_off);
    float* p_attn; cudaGetSymbolAddress((void**)&p_attn, g_attn);
    float* p_tmp;  cudaGetSymbolAddress((void**)&p_tmp,  g_tmp);
    float* p_x;    cudaGetSymbolAddress((void**)&p_x,    g_x);
    __half *p_valh, *p_qh, *p_ql, *p_vh, *p_vl, *p_sh, *p_sl, *p_xh, *p_xl, *p_h1h, *p_h1l, *p_wh;
    cudaGetSymbolAddress((void**)&p_valh, g_valh);
    cudaGetSymbolAddress((void**)&p_qh,  g_qh);
    cudaGetSymbolAddress((void**)&p_ql,  g_ql);
    cudaGetSymbolAddress((void**)&p_vh,  g_vh);
    cudaGetSymbolAddress((void**)&p_vl,  g_vl);
    cudaGetSymbolAddress((void**)&p_sh,  g_sh);
    cudaGetSymbolAddress((void**)&p_sl,  g_sl);
    cudaGetSymbolAddress((void**)&p_xh,  g_xh);
    cudaGetSymbolAddress((void**)&p_xl,  g_xl);
    cudaGetSymbolAddress((void**)&p_h1h, g_h1h);
    cudaGetSymbolAddress((void**)&p_h1l, g_h1l);
    cudaGetSymbolAddress((void**)&p_wh,  g_wh);

    static int smem_set = 0;
    if (!smem_set) {
        cudaFuncSetAttribute(mma_gemm_kernel, cudaFuncAttributeMaxDynamicSharedMemorySize, GSM_TOTAL);
        smem_set = 1;
    }

    const int M = ROWS;
    const int MT = (M + 127) / 128;   // 171

    // 1. build q, v (with fp16 splits)
    {
        size_t total = (size_t)ROWS * DM;
        build_qv_kernel<<<(unsigned)((total + 255) / 256), 256>>>(src, pos, sel_vt);
    }
    // 2. weight conversion (single kernel, fp16 round)
    conv_all_kernel<<<(WTOT + 255) / 256, 256>>>(W_value, W_off, W_attn, W_out, W1, W2);

    // 3. value projection -> fp16 (sampling source)
    mma_gemm_kernel<<<dim3(4, MT), 256, GSM_TOTAL>>>(p_vh, p_vl, p_wh + WOFF_V,
        b_value, nullptr, nullptr, nullptr, p_valh, nullptr, M, DM, DM, 0);
    // 4. fused offsets+attn: B = [Wo; Wa], N=384; cols<256 -> g_off, cols>=256 -> g_attn
    mma_gemm_kernel<<<dim3(6, MT), 256, GSM_TOTAL>>>(p_qh, p_ql, p_wh + WOFF_O,
        b_off, b_attn, p_off, p_attn, nullptr, nullptr, M, DM, DM, 0);
    // 5. softmax
    softmax16_kernel<<<(ROWS * NH + 255) / 256, 256>>>();
    // 6. deformable sampling -> fp16 splits
    sample_kernel<<<ROWS, 256>>>(refpts);
    // 7. output projection -> g_tmp
    mma_gemm_kernel<<<dim3(4, MT), 256, GSM_TOTAL>>>(p_sh, p_sl, p_wh + WOFF_OUT,
        b_out, nullptr, p_tmp, nullptr, nullptr, nullptr, M, DM, DM, 0);
    // 8. x = LN(v + src2) (+ fp16 splits)
    resid_ln_kernel<<<ROWS, 256>>>(p_v, p_tmp, g1, beta1, p_x, p_xh, p_xl);
    // 9. h1 = relu(x @ W1^T + bf1) -> fp16 splits directly (N=1024)
    mma_gemm_kernel<<<dim3(16, MT), 256, GSM_TOTAL>>>(p_xh, p_xl, p_wh + WOFF_1,
        bf1, nullptr, nullptr, nullptr, p_h1h, p_h1l, M, DF, DM, 1);
    // 10. h = h1 @ W2^T + bf2 -> g_tmp (K=1024)
    mma_gemm_kernel<<<dim3(4, MT), 256, GSM_TOTAL>>>(p_h1h, p_h1l, p_wh + WOFF_2,
        bf2, nullptr, p_tmp, nullptr, nullptr, nullptr, M, DM, DF, 0);
    // 11. x = LN(x + h)
    resid_ln_kernel<<<ROWS, 256>>>(p_x, p_tmp, g2, beta2, p_x, nullptr, nullptr);
    // 12. assemble outputs
    {
        size_t total = (size_t)NB * (L_SP + 75 * N_VT + N_VT) * DM;
        write_out_kernel<<<(unsigned)((total + 255) / 256), 256>>>(all_vt, out);
    }
}

// round 8
// speedup vs baseline: 3.6744x; 1.1556x over previous
#include <cuda_runtime.h>
#include <cuda_fp16.h>
#include <math.h>
#include <cstdint>

// ---------------- problem constants ----------------
#define NB     4
#define L_SP   5440
#define N_VT   8
#define LQ     (L_SP + N_VT)      // 5448
#define DM     256
#define DF     1024
#define NH     8
#define DH     32
#define NLEV   4
#define NPTS   4
#define ROWS   (NB * LQ)          // 21792
#define EPSLN  1e-5f

__device__ __constant__ int c_H[NLEV]     = {64, 32, 16, 8};
__device__ __constant__ int c_W[NLEV]     = {64, 32, 16, 8};
__device__ __constant__ int c_start[NLEV] = {0, 4096, 5120, 5376};

// ---------------- scratch (device globals; no allocs) ----------------
static __device__ float g_v   [ (size_t)ROWS * DM ];   // v_in fp32 (residual 1)
static __device__ float g_off [ (size_t)ROWS * DM ];
static __device__ float g_attn[ (size_t)ROWS * 128 ];
static __device__ float g_tmp [ (size_t)ROWS * DM ];
static __device__ float g_x   [ (size_t)ROWS * DM ];

static __device__ __half g_valh[ (size_t)ROWS * DM ];  // value projection (sampling source)
static __device__ __half g_qh [ (size_t)ROWS * DM ];
static __device__ __half g_vh [ (size_t)ROWS * DM ];
static __device__ __half g_sh [ (size_t)ROWS * DM ];
static __device__ __half g_xh [ (size_t)ROWS * DM ];
static __device__ __half g_h1h[ (size_t)ROWS * DF ];

// weights (concatenated fp16): Wv | Wo | Wa | Wout | W1 | W2
#define WOFF_V    0
#define WOFF_O    65536
#define WOFF_A    131072
#define WOFF_OUT  163840
#define WOFF_1    229376
#define WOFF_2    491520
#define WTOT      753664
static __device__ __half g_wh[WTOT];

// ---------------- helpers ----------------
__device__ __forceinline__ uint32_t smem_to_u32(const void* p) {
    uint32_t a;
    asm("{ .reg .u64 t; cvta.to.shared.u64 t, %1; cvt.u32.u64 %0, t; }" : "=r"(a) : "l"(p));
    return a;
}

#define LDSM_X4(r, addr) \
    asm volatile("ldmatrix.sync.aligned.m8n8.x4.shared.b16 {%0,%1,%2,%3}, [%4];" \
        : "=r"((r)[0]), "=r"((r)[1]), "=r"((r)[2]), "=r"((r)[3]) : "r"(addr))

#define MMA_F16(d, a, b) \
    asm volatile("mma.sync.aligned.m16n8k16.row.col.f32.f16.f16.f32 " \
        "{%0,%1,%2,%3}, {%4,%5,%6,%7}, {%8,%9}, {%0,%1,%2,%3};" \
        : "+f"((d)[0]), "+f"((d)[1]), "+f"((d)[2]), "+f"((d)[3]) \
        : "r"((a)[0]), "r"((a)[1]), "r"((a)[2]), "r"((a)[3]), \
          "r"((b)[0]), "r"((b)[1]))

__device__ __forceinline__ void cp_async16(uint32_t dst, const void* src, bool pred) {
    int sz = pred ? 16 : 0;
    asm volatile("cp.async.cg.shared.global [%0], [%1], 16, %2;"
        :: "r"(dst), "l"(src), "r"(sz) : "memory");
}
#define CP_COMMIT() asm volatile("cp.async.commit_group;" ::: "memory")
#define CP_WAIT1()  asm volatile("cp.async.wait_group 1;" ::: "memory")

// swizzled byte offset within rows of 128 bytes
__device__ __forceinline__ uint32_t swz(uint32_t row, uint32_t kb) {
    return row * 128u + (kb ^ ((row & 7u) << 4));
}

// ---------------- pipelined warp-MMA 1-term fp16 GEMM ----------------
// C = Ah @ Bh^T + bias. CTA tile 128x64, BK=64, 256 threads (8 warps, 4m x 2n),
// warp tile 32x32. 2-stage cp.async; stage = 24KB (AH 16K, BH 8K). 3 CTAs/SM.
#define STG_BYTES 24576
#define SB_AH 0
#define SB_BH 16384
#define GSM_TOTAL (2 * STG_BYTES)   // 49152

extern __shared__ char dyn_smem[];

__device__ __forceinline__ void gemm_issue_stage(
    uint32_t sb, const __half* Ah, const __half* Bh,
    int bm, int bn, int k0, int M, int K, int tid, bool active)
{
    // A: 128 rows x 8 segs of 16B = 1024 slots (4 iters over 256 threads)
#pragma unroll
    for (int t = 0; t < 4; t++) {
        int idx = t * 256 + tid;
        int row = idx >> 3, seg = idx & 7;
        uint32_t so = swz((uint32_t)row, (uint32_t)(seg * 16));
        int gm = bm + row;
        bool am = active && (gm < M);
        size_t aoff = am ? ((size_t)gm * K + k0 + seg * 8) : 0;
        cp_async16(sb + SB_AH + so, Ah + aoff, am);
    }
    // B: 64 rows x 8 segs = 512 slots (2 iters)
#pragma unroll
    for (int t = 0; t < 2; t++) {
        int idx = t * 256 + tid;
        int row = idx >> 3, seg = idx & 7;
        uint32_t so = swz((uint32_t)row, (uint32_t)(seg * 16));
        size_t boff = (size_t)(bn + row) * K + k0 + seg * 8;
        cp_async16(sb + SB_BH + so, Bh + boff, active);
    }
}

__global__ void __launch_bounds__(256, 3)
mma_gemm_kernel(const __half* __restrict__ Ah, const __half* __restrict__ Bh,
                const float* __restrict__ bias1, const float* __restrict__ bias2,
                float* __restrict__ C, float* __restrict__ C2,
                __half* __restrict__ Chi,
                int M, int N1, int K, int relu)
{
    const uint32_t s0 = smem_to_u32(dyn_smem);
    const int tid  = threadIdx.x;
    const int wid  = tid >> 5;
    const int lane = tid & 31;
    const int wm   = wid & 3;
    const int wn   = wid >> 2;
    const int bm = blockIdx.y * 128;
    const int bn = blockIdx.x * 64;
    const int Ntot = gridDim.x * 64;

    float acc[2][4][4];
#pragma unroll
    for (int i = 0; i < 2; i++)
#pragma unroll
        for (int j = 0; j < 4; j++)
#pragma unroll
            for (int c = 0; c < 4; c++) acc[i][j][c] = 0.f;

    const int nch = K >> 6;

#pragma unroll
    for (int s = 0; s < 2; s++) {
        gemm_issue_stage(s0 + s * STG_BYTES, Ah, Bh, bm, bn, s << 6, M, K, tid, s < nch);
        CP_COMMIT();
    }

    for (int ch = 0; ch < nch; ch++) {
        CP_WAIT1();
        __syncthreads();
        const uint32_t sb = s0 + (ch & 1) * STG_BYTES;
        const uint32_t sAH = sb + SB_AH, sBH = sb + SB_BH;

#pragma unroll
        for (int ks = 0; ks < 4; ks++) {
            uint32_t a_h[2][4];
            {
                uint32_t rA = (uint32_t)(wm * 32 + (lane & 15));
                uint32_t kbA = (uint32_t)(ks * 32 + ((lane >> 4) << 4));
#pragma unroll
                for (int mt = 0; mt < 2; mt++) {
                    uint32_t off = swz(rA + mt * 16, kbA);
                    LDSM_X4(a_h[mt], sAH + off);
                }
            }
            uint32_t b_h[4][2];
            {
                uint32_t rB = (uint32_t)((lane & 7) + ((lane >> 4) << 3));
                uint32_t kbB = (uint32_t)(ks * 32 + (((lane >> 3) & 1) << 4));
#pragma unroll
                for (int np = 0; np < 2; np++) {
                    uint32_t row = (uint32_t)(wn * 32 + np * 16) + rB;
                    uint32_t off = swz(row, kbB);
                    uint32_t r4[4];
                    LDSM_X4(r4, sBH + off);
                    b_h[np * 2][0] = r4[0]; b_h[np * 2][1] = r4[1];
                    b_h[np * 2 + 1][0] = r4[2]; b_h[np * 2 + 1][1] = r4[3];
                }
            }
#pragma unroll
            for (int mt = 0; mt < 2; mt++)
#pragma unroll
                for (int nt = 0; nt < 4; nt++)
                    MMA_F16(acc[mt][nt], a_h[mt], b_h[nt]);
        }
        __syncthreads();
        int nxt = ch + 2;
        gemm_issue_stage(s0 + (nxt & 1) * STG_BYTES, Ah, Bh,
                         bm, bn, nxt << 6, M, K, tid, nxt < nch);
        CP_COMMIT();
    }

    // epilogue
    const int mrow0 = bm + wm * 32;
    const int ncol0 = bn + wn * 32;
#pragma unroll
    for (int mt = 0; mt < 2; mt++) {
        int r0 = mrow0 + mt * 16 + (lane >> 2);
        int r1 = r0 + 8;
#pragma unroll
        for (int nt = 0; nt < 4; nt++) {
            int n = ncol0 + nt * 8 + (lane & 3) * 2;
            float* dst; int stride; int nc;
            float bi0, bi1;
            if (C2 && n >= N1) {
                nc = n - N1; dst = C2; stride = Ntot - N1;
                bi0 = __ldg(&bias2[nc]); bi1 = __ldg(&bias2[nc + 1]);
            } else {
                nc = n; dst = C; stride = N1;
                bi0 = __ldg(&bias1[nc]); bi1 = __ldg(&bias1[nc + 1]);
            }
            float v00 = acc[mt][nt][0] + bi0, v01 = acc[mt][nt][1] + bi1;
            float v10 = acc[mt][nt][2] + bi0, v11 = acc[mt][nt][3] + bi1;
            if (relu) {
                v00 = fmaxf(v00, 0.f); v01 = fmaxf(v01, 0.f);
                v10 = fmaxf(v10, 0.f); v11 = fmaxf(v11, 0.f);
            }
            if (C) {
                if (r0 < M) *(float2*)(dst + (size_t)r0 * stride + nc) = make_float2(v00, v01);
                if (r1 < M) *(float2*)(dst + (size_t)r1 * stride + nc) = make_float2(v10, v11);
            } else {
                if (r0 < M)
                    *(__half2*)(Chi + (size_t)r0 * Ntot + n) =
                        __halves2half2(__float2half(v00), __float2half(v01));
                if (r1 < M)
                    *(__half2*)(Chi + (size_t)r1 * Ntot + n) =
                        __halves2half2(__float2half(v10), __float2half(v11));
            }
        }
    }
}

// ---------------- build q and v_in ----------------
__global__ void build_qv_kernel(const float* __restrict__ src,
                                const float* __restrict__ pos,
                                const float* __restrict__ sel_vt)
{
    size_t idx = (size_t)blockIdx.x * blockDim.x + threadIdx.x;
    size_t total = (size_t)ROWS * DM;
    if (idx >= total) return;
    size_t row = idx / DM;
    int d = (int)(idx % DM);
    int n = (int)(row / LQ);
    int r = (int)(row % LQ);
    float qv, vv;
    if (r < L_SP) {
        size_t si = ((size_t)n * L_SP + r) * DM + d;
        float s = src[si];
        qv = s + pos[si];
        vv = s;
    } else {
        size_t si = ((size_t)n * N_VT + (r - L_SP)) * DM + d;
        float s = sel_vt[si];
        qv = s; vv = s;
    }
    g_v[idx] = vv;
    g_qh[idx] = __float2half(qv);
    g_vh[idx] = __float2half(vv);
}

// ---------------- all weight conversions in ONE kernel ----------------
__global__ void conv_all_kernel(const float* __restrict__ Wv, const float* __restrict__ Wo,
                                const float* __restrict__ Wa, const float* __restrict__ Wout,
                                const float* __restrict__ W1, const float* __restrict__ W2)
{
    int i = blockIdx.x * blockDim.x + threadIdx.x;
    if (i >= WTOT) return;
    float x;
    if      (i < WOFF_O)   x = Wv  [i];
    else if (i < WOFF_A)   x = Wo  [i - WOFF_O];
    else if (i < WOFF_OUT) x = Wa  [i - WOFF_A];
    else if (i < WOFF_1)   x = Wout[i - WOFF_OUT];
    else if (i < WOFF_2)   x = W1  [i - WOFF_1];
    else                   x = W2  [i - WOFF_2];
    g_wh[i] = __float2half(x);
}

// ---------------- softmax over 16 points per (row, head) ----------------
__global__ void softmax16_kernel()
{
    int t = blockIdx.x * blockDim.x + threadIdx.x;
    if (t >= ROWS * NH) return;
    size_t base = (size_t)(t >> 3) * 128 + (t & 7) * 16;
    float v[16];
    float mx = -1e30f;
#pragma unroll
    for (int i = 0; i < 16; i++) { v[i] = g_attn[base + i]; mx = fmaxf(mx, v[i]); }
    float s = 0.f;
#pragma unroll
    for (int i = 0; i < 16; i++) { v[i] = __expf(v[i] - mx); s += v[i]; }
    float inv = 1.f / s;
#pragma unroll
    for (int i = 0; i < 16; i++) g_attn[base + i] = v[i] * inv;
}

// ---------------- deformable sampling (fp16 value) -> fp16 ----------------
__global__ void sample_kernel(const float* __restrict__ ref)
{
    const int row = blockIdx.x;
    const int m   = threadIdx.x >> 5;
    const int d   = threadIdx.x & 31;
    const int n   = row / LQ;

    const float* refp = ref + (size_t)row * (NLEV * 2);
    const float* offp = g_off + (size_t)row * DM + m * (NLEV * NPTS * 2);
    const float* attp = g_attn + (size_t)row * 128 + m * 16;
    const __half* valn = g_valh + (size_t)n * LQ * DM;

    float acc = 0.f;
#pragma unroll
    for (int l = 0; l < NLEV; l++) {
        const int H = c_H[l], W = c_W[l], st = c_start[l];
        const float rx = refp[l * 2 + 0];
        const float ry = refp[l * 2 + 1];
#pragma unroll
        for (int p = 0; p < NPTS; p++) {
            const float ox = offp[(l * NPTS + p) * 2 + 0];
            const float oy = offp[(l * NPTS + p) * 2 + 1];
            const float a  = attp[l * NPTS + p];
            const float x = rx * W + ox - 0.5f;
            const float y = ry * H + oy - 0.5f;
            const float x0f = floorf(x), y0f = floorf(y);
            const float wx = x - x0f, wy = y - y0f;
            const int x0 = (int)x0f, y0 = (int)y0f;
            const int x1 = x0 + 1,   y1 = y0 + 1;
            const bool vx0 = (x0 >= 0) & (x0 < W);
            const bool vx1 = (x1 >= 0) & (x1 < W);
            const bool vy0 = (y0 >= 0) & (y0 < H);
            const bool vy1 = (y1 >= 0) & (y1 < H);
            const float w00 = (1.f - wx) * (1.f - wy);
            const float w10 = wx * (1.f - wy);
            const float w01 = (1.f - wx) * wy;
            const float w11 = wx * wy;
            if (vx0 & vy0) acc += a * w00 * __half2float(valn[((size_t)(st + y0 * W + x0)) * DM + m * DH + d]);
            if (vx1 & vy0) acc += a * w10 * __half2float(valn[((size_t)(st + y0 * W + x1)) * DM + m * DH + d]);
            if (vx0 & vy1) acc += a * w01 * __half2float(valn[((size_t)(st + y1 * W + x0)) * DM + m * DH + d]);
            if (vx1 & vy1) acc += a * w11 * __half2float(valn[((size_t)(st + y1 * W + x1)) * DM + m * DH + d]);
        }
    }
    g_sh[(size_t)row * DM + m * DH + d] = __float2half(acc);
}

// ---------------- residual + LayerNorm (+ optional fp16 out) ----------------
__global__ void resid_ln_kernel(const float* __restrict__ a,
                                const float* __restrict__ b,
                                const float* __restrict__ g,
                                const float* __restrict__ beta,
                                float* __restrict__ out,
                                __half* __restrict__ outH)
{
    __shared__ float red[64];
    const int row = blockIdx.x;
    const int t = threadIdx.x;
    size_t base = (size_t)row * DM;
    float x = a[base + t] + b[base + t];

    float s = x;
#pragma unroll
    for (int o = 16; o > 0; o >>= 1) s += __shfl_xor_sync(0xffffffffu, s, o);
    if ((t & 31) == 0) red[t >> 5] = s;
    __syncthreads();
    if (t < 8) {
        float v = red[t];
#pragma unroll
        for (int o = 4; o > 0; o >>= 1) v += __shfl_xor_sync(0xffu, v, o);
        if (t == 0) red[32] = v;
    }
    __syncthreads();
    float mean = red[32] * (1.f / DM);

    float xc = x - mean;
    float sq = xc * xc;
#pragma unroll
    for (int o = 16; o > 0; o >>= 1) sq += __shfl_xor_sync(0xffffffffu, sq, o);
    if ((t & 31) == 0) red[t >> 5] = sq;
    __syncthreads();
    if (t < 8) {
        float v = red[t];
#pragma unroll
        for (int o = 4; o > 0; o >>= 1) v += __shfl_xor_sync(0xffu, v, o);
        if (t == 0) red[33] = v;
    }
    __syncthreads();
    float var = red[33] * (1.f / DM);
    float inv = rsqrtf(var + EPSLN);
    float y = g[t] * xc * inv + beta[t];
    out[base + t] = y;
    if (outH) outH[base + t] = __float2half(y);
}

// ---------------- assemble final output ----------------
__global__ void write_out_kernel(const float* __restrict__ all_vt, float* __restrict__ out)
{
    const size_t P1 = (size_t)NB * L_SP * DM;
    const size_t P2 = (size_t)NB * 75 * N_VT * DM;
    const size_t P3 = (size_t)NB * N_VT * DM;
    size_t idx = (size_t)blockIdx.x * blockDim.x + threadIdx.x;
    if (idx < P1) {
        size_t row = idx / DM; int d = (int)(idx % DM);
        int n = (int)(row / L_SP), r = (int)(row % L_SP);
        out[idx] = g_x[((size_t)n * LQ + r) * DM + d];
    } else if (idx < P1 + P2) {
        out[idx] = all_vt[idx - P1];
    } else if (idx < P1 + P2 + P3) {
        size_t k = idx - P1 - P2;
        size_t row = k / DM; int d = (int)(k % DM);
        int n = (int)(row / N_VT), r = (int)(row % N_VT);
        out[idx] = g_x[((size_t)n * LQ + L_SP + r) * DM + d];
    }
}

// ---------------- launch ----------------
extern "C" void kernel_launch(void* const* d_in, const int* in_sizes, int n_in,
                              void* d_out, int out_size)
{
    const float* src     = (const float*)d_in[0];
    const float* pos     = (const float*)d_in[1];
    const float* refpts  = (const float*)d_in[2];
    const float* all_vt  = (const float*)d_in[6];
    const float* sel_vt  = (const float*)d_in[7];
    const float* W_value = (const float*)d_in[8];
    const float* b_value = (const float*)d_in[9];
    const float* W_off   = (const float*)d_in[10];
    const float* b_off   = (const float*)d_in[11];
    const float* W_attn  = (const float*)d_in[12];
    const float* b_attn  = (const float*)d_in[13];
    const float* W_out   = (const float*)d_in[14];
    const float* b_out   = (const float*)d_in[15];
    const float* g1      = (const float*)d_in[16];
    const float* beta1   = (const float*)d_in[17];
    const float* W1      = (const float*)d_in[18];
    const float* bf1     = (const float*)d_in[19];
    const float* W2      = (const float*)d_in[20];
    const float* bf2     = (const float*)d_in[21];
    const float* g2      = (const float*)d_in[22];
    const float* beta2   = (const float*)d_in[23];
    float* out = (float*)d_out;

    float* p_v;    cudaGetSymbolAddress((void**)&p_v,    g_v);
    float* p_off;  cudaGetSymbolAddress((void**)&p_off,  g_off);
    float* p_attn; cudaGetSymbolAddress((void**)&p_attn, g_attn);
    float* p_tmp;  cudaGetSymbolAddress((void**)&p_tmp,  g_tmp);
    float* p_x;    cudaGetSymbolAddress((void**)&p_x,    g_x);
    __half *p_valh, *p_qh, *p_vh, *p_sh, *p_xh, *p_h1h, *p_wh;
    cudaGetSymbolAddress((void**)&p_valh, g_valh);
    cudaGetSymbolAddress((void**)&p_qh,  g_qh);
    cudaGetSymbolAddress((void**)&p_vh,  g_vh);
    cudaGetSymbolAddress((void**)&p_sh,  g_sh);
    cudaGetSymbolAddress((void**)&p_xh,  g_xh);
    cudaGetSymbolAddress((void**)&p_h1h, g_h1h);
    cudaGetSymbolAddress((void**)&p_wh,  g_wh);

    static int smem_set = 0;
    if (!smem_set) {
        cudaFuncSetAttribute(mma_gemm_kernel, cudaFuncAttributeMaxDynamicSharedMemorySize, GSM_TOTAL);
        smem_set = 1;
    }

    const int M = ROWS;
    const int MT = (M + 127) / 128;   // 171

    // 1. build q, v
    {
        size_t total = (size_t)ROWS * DM;
        build_qv_kernel<<<(unsigned)((total + 255) / 256), 256>>>(src, pos, sel_vt);
    }
    // 2. weight conversion
    conv_all_kernel<<<(WTOT + 255) / 256, 256>>>(W_value, W_off, W_attn, W_out, W1, W2);

    // 3. value projection -> fp16 (sampling source)
    mma_gemm_kernel<<<dim3(4, MT), 256, GSM_TOTAL>>>(p_vh, p_wh + WOFF_V,
        b_value, nullptr, nullptr, nullptr, p_valh, M, DM, DM, 0);
    // 4. fused offsets+attn: B = [Wo; Wa], N=384; cols<256 -> g_off, cols>=256 -> g_attn
    mma_gemm_kernel<<<dim3(6, MT), 256, GSM_TOTAL>>>(p_qh, p_wh + WOFF_O,
        b_off, b_attn, p_off, p_attn, nullptr, M, DM, DM, 0);
    // 5. softmax
    softmax16_kernel<<<(ROWS * NH + 255) / 256, 256>>>();
    // 6. deformable sampling -> fp16
    sample_kernel<<<ROWS, 256>>>(refpts);
    // 7. output projection -> g_tmp
    mma_gemm_kernel<<<dim3(4, MT), 256, GSM_TOTAL>>>(p_sh, p_wh + WOFF_OUT,
        b_out, nullptr, p_tmp, nullptr, nullptr, M, DM, DM, 0);
    // 8. x = LN(v + src2) (+ fp16)
    resid_ln_kernel<<<ROWS, 256>>>(p_v, p_tmp, g1, beta1, p_x, p_xh);
    // 9. h1 = relu(x @ W1^T + bf1) -> fp16 (N=1024)
    mma_gemm_kernel<<<dim3(16, MT), 256, GSM_TOTAL>>>(p_xh, p_wh + WOFF_1,
        bf1, nullptr, nullptr, nullptr, p_h1h, M, DF, DM, 1);
    // 10. h = h1 @ W2^T + bf2 -> g_tmp (K=1024)
    mma_gemm_kernel<<<dim3(4, MT), 256, GSM_TOTAL>>>(p_h1h, p_wh + WOFF_2,
        bf2, nullptr, p_tmp, nullptr, nullptr, M, DM, DF, 0);
    // 11. x = LN(x + h)
    resid_ln_kernel<<<ROWS, 256>>>(p_x, p_tmp, g2, beta2, p_x, nullptr);
    // 12. assemble outputs
    {
        size_t total = (size_t)NB * (L_SP + 75 * N_VT + N_VT) * DM;
        write_out_kernel<<<(unsigned)((total + 255) / 256), 256>>>(all_vt, out);
    }
}

// round 9
// speedup vs baseline: 4.2668x; 1.1612x over previous
#include <cuda_runtime.h>
#include <cuda_fp16.h>
#include <math.h>
#include <cstdint>

// ---------------- problem constants ----------------
#define NB     4
#define L_SP   5440
#define N_VT   8
#define LQ     (L_SP + N_VT)      // 5448
#define DM     256
#define DF     1024
#define NH     8
#define DH     32
#define NLEV   4
#define NPTS   4
#define ROWS   (NB * LQ)          // 21792
#define EPSLN  1e-5f

__device__ __constant__ int c_H[NLEV]     = {64, 32, 16, 8};
__device__ __constant__ int c_W[NLEV]     = {64, 32, 16, 8};
__device__ __constant__ int c_start[NLEV] = {0, 4096, 5120, 5376};

// ---------------- scratch (device globals; no allocs) ----------------
static __device__ float g_v   [ (size_t)ROWS * DM ];   // v_in fp32 (residual 1)
static __device__ float g_off [ (size_t)ROWS * DM ];
static __device__ float g_attn[ (size_t)ROWS * 128 ];  // raw logits (softmax fused into sample)
static __device__ float g_tmp [ (size_t)ROWS * DM ];
static __device__ float g_x   [ (size_t)ROWS * DM ];

static __device__ __half g_valh[ (size_t)ROWS * DM ];  // value projection (sampling source)
static __device__ __half g_qh [ (size_t)ROWS * DM ];
static __device__ __half g_vh [ (size_t)ROWS * DM ];
static __device__ __half g_sh [ (size_t)ROWS * DM ];
static __device__ __half g_xh [ (size_t)ROWS * DM ];
static __device__ __half g_h1h[ (size_t)ROWS * DF ];

// weights (concatenated fp16): Wv | Wo | Wa | Wout | W1 | W2
#define WOFF_V    0
#define WOFF_O    65536
#define WOFF_A    131072
#define WOFF_OUT  163840
#define WOFF_1    229376
#define WOFF_2    491520
#define WTOT      753664
static __device__ __half g_wh[WTOT];

// ---------------- helpers ----------------
__device__ __forceinline__ uint32_t smem_to_u32(const void* p) {
    uint32_t a;
    asm("{ .reg .u64 t; cvta.to.shared.u64 t, %1; cvt.u32.u64 %0, t; }" : "=r"(a) : "l"(p));
    return a;
}

#define LDSM_X4(r, addr) \
    asm volatile("ldmatrix.sync.aligned.m8n8.x4.shared.b16 {%0,%1,%2,%3}, [%4];" \
        : "=r"((r)[0]), "=r"((r)[1]), "=r"((r)[2]), "=r"((r)[3]) : "r"(addr))

#define MMA_F16(d, a, b) \
    asm volatile("mma.sync.aligned.m16n8k16.row.col.f32.f16.f16.f32 " \
        "{%0,%1,%2,%3}, {%4,%5,%6,%7}, {%8,%9}, {%0,%1,%2,%3};" \
        : "+f"((d)[0]), "+f"((d)[1]), "+f"((d)[2]), "+f"((d)[3]) \
        : "r"((a)[0]), "r"((a)[1]), "r"((a)[2]), "r"((a)[3]), \
          "r"((b)[0]), "r"((b)[1]))

__device__ __forceinline__ void cp_async16(uint32_t dst, const void* src, bool pred) {
    int sz = pred ? 16 : 0;
    asm volatile("cp.async.cg.shared.global [%0], [%1], 16, %2;"
        :: "r"(dst), "l"(src), "r"(sz) : "memory");
}
#define CP_COMMIT() asm volatile("cp.async.commit_group;" ::: "memory")
#define CP_WAIT1()  asm volatile("cp.async.wait_group 1;" ::: "memory")

// swizzled byte offset within rows of 128 bytes
__device__ __forceinline__ uint32_t swz(uint32_t row, uint32_t kb) {
    return row * 128u + (kb ^ ((row & 7u) << 4));
}

// ---------------- pipelined warp-MMA 1-term fp16 GEMM ----------------
// C = Ah @ Bh^T + bias. CTA tile 128x64, BK=64, 256 threads (8 warps, 4m x 2n),
// warp tile 32x32. 2-stage cp.async; stage = 24KB (AH 16K, BH 8K). 3 CTAs/SM.
#define STG_BYTES 24576
#define SB_AH 0
#define SB_BH 16384
#define GSM_TOTAL (2 * STG_BYTES)   // 49152

extern __shared__ char dyn_smem[];

__device__ __forceinline__ void gemm_issue_stage(
    uint32_t sb, const __half* Ah, const __half* Bh,
    int bm, int bn, int k0, int M, int K, int tid, bool active)
{
#pragma unroll
    for (int t = 0; t < 4; t++) {
        int idx = t * 256 + tid;
        int row = idx >> 3, seg = idx & 7;
        uint32_t so = swz((uint32_t)row, (uint32_t)(seg * 16));
        int gm = bm + row;
        bool am = active && (gm < M);
        size_t aoff = am ? ((size_t)gm * K + k0 + seg * 8) : 0;
        cp_async16(sb + SB_AH + so, Ah + aoff, am);
    }
#pragma unroll
    for (int t = 0; t < 2; t++) {
        int idx = t * 256 + tid;
        int row = idx >> 3, seg = idx & 7;
        uint32_t so = swz((uint32_t)row, (uint32_t)(seg * 16));
        size_t boff = (size_t)(bn + row) * K + k0 + seg * 8;
        cp_async16(sb + SB_BH + so, Bh + boff, active);
    }
}

__global__ void __launch_bounds__(256, 3)
mma_gemm_kernel(const __half* __restrict__ Ah, const __half* __restrict__ Bh,
                const float* __restrict__ bias1, const float* __restrict__ bias2,
                float* __restrict__ C, float* __restrict__ C2,
                __half* __restrict__ Chi,
                int M, int N1, int K, int relu)
{
    const uint32_t s0 = smem_to_u32(dyn_smem);
    const int tid  = threadIdx.x;
    const int wid  = tid >> 5;
    const int lane = tid & 31;
    const int wm   = wid & 3;
    const int wn   = wid >> 2;
    const int bm = blockIdx.y * 128;
    const int bn = blockIdx.x * 64;
    const int Ntot = gridDim.x * 64;

    float acc[2][4][4];
#pragma unroll
    for (int i = 0; i < 2; i++)
#pragma unroll
        for (int j = 0; j < 4; j++)
#pragma unroll
            for (int c = 0; c < 4; c++) acc[i][j][c] = 0.f;

    const int nch = K >> 6;

#pragma unroll
    for (int s = 0; s < 2; s++) {
        gemm_issue_stage(s0 + s * STG_BYTES, Ah, Bh, bm, bn, s << 6, M, K, tid, s < nch);
        CP_COMMIT();
    }

    for (int ch = 0; ch < nch; ch++) {
        CP_WAIT1();
        __syncthreads();
        const uint32_t sb = s0 + (ch & 1) * STG_BYTES;
        const uint32_t sAH = sb + SB_AH, sBH = sb + SB_BH;

#pragma unroll
        for (int ks = 0; ks < 4; ks++) {
            uint32_t a_h[2][4];
            {
                uint32_t rA = (uint32_t)(wm * 32 + (lane & 15));
                uint32_t kbA = (uint32_t)(ks * 32 + ((lane >> 4) << 4));
#pragma unroll
                for (int mt = 0; mt < 2; mt++) {
                    uint32_t off = swz(rA + mt * 16, kbA);
                    LDSM_X4(a_h[mt], sAH + off);
                }
            }
            uint32_t b_h[4][2];
            {
                uint32_t rB = (uint32_t)((lane & 7) + ((lane >> 4) << 3));
                uint32_t kbB = (uint32_t)(ks * 32 + (((lane >> 3) & 1) << 4));
#pragma unroll
                for (int np = 0; np < 2; np++) {
                    uint32_t row = (uint32_t)(wn * 32 + np * 16) + rB;
                    uint32_t off = swz(row, kbB);
                    uint32_t r4[4];
                    LDSM_X4(r4, sBH + off);
                    b_h[np * 2][0] = r4[0]; b_h[np * 2][1] = r4[1];
                    b_h[np * 2 + 1][0] = r4[2]; b_h[np * 2 + 1][1] = r4[3];
                }
            }
#pragma unroll
            for (int mt = 0; mt < 2; mt++)
#pragma unroll
                for (int nt = 0; nt < 4; nt++)
                    MMA_F16(acc[mt][nt], a_h[mt], b_h[nt]);
        }
        __syncthreads();
        int nxt = ch + 2;
        gemm_issue_stage(s0 + (nxt & 1) * STG_BYTES, Ah, Bh,
                         bm, bn, nxt << 6, M, K, tid, nxt < nch);
        CP_COMMIT();
    }

    // epilogue
    const int mrow0 = bm + wm * 32;
    const int ncol0 = bn + wn * 32;
#pragma unroll
    for (int mt = 0; mt < 2; mt++) {
        int r0 = mrow0 + mt * 16 + (lane >> 2);
        int r1 = r0 + 8;
#pragma unroll
        for (int nt = 0; nt < 4; nt++) {
            int n = ncol0 + nt * 8 + (lane & 3) * 2;
            float* dst; int stride; int nc;
            float bi0, bi1;
            if (C2 && n >= N1) {
                nc = n - N1; dst = C2; stride = Ntot - N1;
                bi0 = __ldg(&bias2[nc]); bi1 = __ldg(&bias2[nc + 1]);
            } else {
                nc = n; dst = C; stride = N1;
                bi0 = __ldg(&bias1[nc]); bi1 = __ldg(&bias1[nc + 1]);
            }
            float v00 = acc[mt][nt][0] + bi0, v01 = acc[mt][nt][1] + bi1;
            float v10 = acc[mt][nt][2] + bi0, v11 = acc[mt][nt][3] + bi1;
            if (relu) {
                v00 = fmaxf(v00, 0.f); v01 = fmaxf(v01, 0.f);
                v10 = fmaxf(v10, 0.f); v11 = fmaxf(v11, 0.f);
            }
            if (C) {
                if (r0 < M) *(float2*)(dst + (size_t)r0 * stride + nc) = make_float2(v00, v01);
                if (r1 < M) *(float2*)(dst + (size_t)r1 * stride + nc) = make_float2(v10, v11);
            } else {
                if (r0 < M)
                    *(__half2*)(Chi + (size_t)r0 * Ntot + n) =
                        __halves2half2(__float2half(v00), __float2half(v01));
                if (r1 < M)
                    *(__half2*)(Chi + (size_t)r1 * Ntot + n) =
                        __halves2half2(__float2half(v10), __float2half(v11));
            }
        }
    }
}

// ---------------- build q and v_in ----------------
__global__ void build_qv_kernel(const float* __restrict__ src,
                                const float* __restrict__ pos,
                                const float* __restrict__ sel_vt)
{
    size_t idx = (size_t)blockIdx.x * blockDim.x + threadIdx.x;
    size_t total = (size_t)ROWS * DM;
    if (idx >= total) return;
    size_t row = idx / DM;
    int d = (int)(idx % DM);
    int n = (int)(row / LQ);
    int r = (int)(row % LQ);
    float qv, vv;
    if (r < L_SP) {
        size_t si = ((size_t)n * L_SP + r) * DM + d;
        float s = src[si];
        qv = s + pos[si];
        vv = s;
    } else {
        size_t si = ((size_t)n * N_VT + (r - L_SP)) * DM + d;
        float s = sel_vt[si];
        qv = s; vv = s;
    }
    g_v[idx] = vv;
    g_qh[idx] = __float2half(qv);
    g_vh[idx] = __float2half(vv);
}

// ---------------- all weight conversions in ONE kernel ----------------
__global__ void conv_all_kernel(const float* __restrict__ Wv, const float* __restrict__ Wo,
                                const float* __restrict__ Wa, const float* __restrict__ Wout,
                                const float* __restrict__ W1, const float* __restrict__ W2)
{
    int i = blockIdx.x * blockDim.x + threadIdx.x;
    if (i >= WTOT) return;
    float x;
    if      (i < WOFF_O)   x = Wv  [i];
    else if (i < WOFF_A)   x = Wo  [i - WOFF_O];
    else if (i < WOFF_OUT) x = Wa  [i - WOFF_A];
    else if (i < WOFF_1)   x = Wout[i - WOFF_OUT];
    else if (i < WOFF_2)   x = W1  [i - WOFF_1];
    else                   x = W2  [i - WOFF_2];
    g_wh[i] = __float2half(x);
}

// ---------------- deformable sampling + fused softmax ----------------
// block = row (21792), warp = head. Lanes 0-15 handle dims [0,32) as half2 for
// point p=2*pp; lanes 16-31 same dims for point p=2*pp+1. Branch-free gathers
// (clamped index, validity folded into weight). shfl_xor(16) combines the pair.
__global__ void __launch_bounds__(256) sample_kernel(const float* __restrict__ ref)
{
    const int row = blockIdx.x;
    const int m    = threadIdx.x >> 5;
    const int lane = threadIdx.x & 31;
    const int psel = lane >> 4;        // which point of the pair
    const int dp   = lane & 15;        // half2 index within head (dims 2dp,2dp+1)
    const int n    = row / LQ;

    const float* refp = ref + (size_t)row * (NLEV * 2);
    const float* offp = g_off + (size_t)row * DM + m * (NLEV * NPTS * 2);
    const float* attp = g_attn + (size_t)row * 128 + m * 16;
    const __half2* valn = (const __half2*)(g_valh + (size_t)n * LQ * DM);
    const int hoff = m * (DH / 2) + dp;   // half2 offset within a value row

    // fused softmax over this head's 16 logits (every lane computes; L1-broadcast)
    float a16[16];
    float mx = -1e30f;
#pragma unroll
    for (int i = 0; i < 16; i++) { a16[i] = __ldg(&attp[i]); mx = fmaxf(mx, a16[i]); }
    float ssum = 0.f;
#pragma unroll
    for (int i = 0; i < 16; i++) { a16[i] = __expf(a16[i] - mx); ssum += a16[i]; }
    const float sinv = 1.f / ssum;

    float accx = 0.f, accy = 0.f;
#pragma unroll
    for (int l = 0; l < NLEV; l++) {
        const int H = c_H[l], W = c_W[l], st = c_start[l];
        const float rx = refp[l * 2 + 0];
        const float ry = refp[l * 2 + 1];
#pragma unroll
        for (int pp = 0; pp < 2; pp++) {
            const int p = pp * 2 + psel;
            const float ox = offp[(l * NPTS + p) * 2 + 0];
            const float oy = offp[(l * NPTS + p) * 2 + 1];
            const float a  = a16[l * NPTS + p] * sinv;
            const float x = rx * W + ox - 0.5f;
            const float y = ry * H + oy - 0.5f;
            const float x0f = floorf(x), y0f = floorf(y);
            const float wx = x - x0f, wy = y - y0f;
            const int x0 = (int)x0f, y0 = (int)y0f;
            const int x1 = x0 + 1,   y1 = y0 + 1;
            const float vx0 = (x0 >= 0 && x0 < W) ? 1.f : 0.f;
            const float vx1 = (x1 >= 0 && x1 < W) ? 1.f : 0.f;
            const float vy0 = (y0 >= 0 && y0 < H) ? 1.f : 0.f;
            const float vy1 = (y1 >= 0 && y1 < H) ? 1.f : 0.f;
            const int x0c = min(max(x0, 0), W - 1), x1c = min(max(x1, 0), W - 1);
            const int y0c = min(max(y0, 0), H - 1), y1c = min(max(y1, 0), H - 1);
            const float c00 = a * (1.f - wx) * (1.f - wy) * vx0 * vy0;
            const float c10 = a * wx * (1.f - wy) * vx1 * vy0;
            const float c01 = a * (1.f - wx) * wy * vx0 * vy1;
            const float c11 = a * wx * wy * vx1 * vy1;
            const int rb0 = st + y0c * W, rb1 = st + y1c * W;
            // branch-free gathers (all four always issued -> deep MLP)
            __half2 h00 = valn[(size_t)(rb0 + x0c) * (DM / 2) + hoff];
            __half2 h10 = valn[(size_t)(rb0 + x1c) * (DM / 2) + hoff];
            __half2 h01 = valn[(size_t)(rb1 + x0c) * (DM / 2) + hoff];
            __half2 h11 = valn[(size_t)(rb1 + x1c) * (DM / 2) + hoff];
            float2 f00 = __half22float2(h00), f10 = __half22float2(h10);
            float2 f01 = __half22float2(h01), f11 = __half22float2(h11);
            accx += c00 * f00.x + c10 * f10.x + c01 * f01.x + c11 * f11.x;
            accy += c00 * f00.y + c10 * f10.y + c01 * f01.y + c11 * f11.y;
        }
    }
    // combine point-pair partners
    accx += __shfl_xor_sync(0xffffffffu, accx, 16);
    accy += __shfl_xor_sync(0xffffffffu, accy, 16);
    if (psel == 0) {
        __half2* dst = (__half2*)(g_sh + (size_t)row * DM + m * DH) + dp;
        *dst = __halves2half2(__float2half(accx), __float2half(accy));
    }
}

// ---------------- residual + LayerNorm (+ optional fp16 out) ----------------
__global__ void resid_ln_kernel(const float* __restrict__ a,
                                const float* __restrict__ b,
                                const float* __restrict__ g,
                                const float* __restrict__ beta,
                                float* __restrict__ out,
                                __half* __restrict__ outH)
{
    __shared__ float red[64];
    const int row = blockIdx.x;
    const int t = threadIdx.x;
    size_t base = (size_t)row * DM;
    float x = a[base + t] + b[base + t];

    float s = x;
#pragma unroll
    for (int o = 16; o > 0; o >>= 1) s += __shfl_xor_sync(0xffffffffu, s, o);
    if ((t & 31) == 0) red[t >> 5] = s;
    __syncthreads();
    if (t < 8) {
        float v = red[t];
#pragma unroll
        for (int o = 4; o > 0; o >>= 1) v += __shfl_xor_sync(0xffu, v, o);
        if (t == 0) red[32] = v;
    }
    __syncthreads();
    float mean = red[32] * (1.f / DM);

    float xc = x - mean;
    float sq = xc * xc;
#pragma unroll
    for (int o = 16; o > 0; o >>= 1) sq += __shfl_xor_sync(0xffffffffu, sq, o);
    if ((t & 31) == 0) red[t >> 5] = sq;
    __syncthreads();
    if (t < 8) {
        float v = red[t];
#pragma unroll
        for (int o = 4; o > 0; o >>= 1) v += __shfl_xor_sync(0xffu, v, o);
        if (t == 0) red[33] = v;
    }
    __syncthreads();
    float var = red[33] * (1.f / DM);
    float inv = rsqrtf(var + EPSLN);
    float y = g[t] * xc * inv + beta[t];
    out[base + t] = y;
    if (outH) outH[base + t] = __float2half(y);
}

// ---------------- final residual + LayerNorm writing straight to d_out ----------------
__global__ void resid_ln_out_kernel(const float* __restrict__ a,
                                    const float* __restrict__ b,
                                    const float* __restrict__ g,
                                    const float* __restrict__ beta,
                                    float* __restrict__ out)
{
    __shared__ float red[64];
    const int row = blockIdx.x;
    const int t = threadIdx.x;
    size_t base = (size_t)row * DM;
    float x = a[base + t] + b[base + t];

    float s = x;
#pragma unroll
    for (int o = 16; o > 0; o >>= 1) s += __shfl_xor_sync(0xffffffffu, s, o);
    if ((t & 31) == 0) red[t >> 5] = s;
    __syncthreads();
    if (t < 8) {
        float v = red[t];
#pragma unroll
        for (int o = 4; o > 0; o >>= 1) v += __shfl_xor_sync(0xffu, v, o);
        if (t == 0) red[32] = v;
    }
    __syncthreads();
    float mean = red[32] * (1.f / DM);

    float xc = x - mean;
    float sq = xc * xc;
#pragma unroll
    for (int o = 16; o > 0; o >>= 1) sq += __shfl_xor_sync(0xffffffffu, sq, o);
    if ((t & 31) == 0) red[t >> 5] = sq;
    __syncthreads();
    if (t < 8) {
        float v = red[t];
#pragma unroll
        for (int o = 4; o > 0; o >>= 1) v += __shfl_xor_sync(0xffu, v, o);
        if (t == 0) red[33] = v;
    }
    __syncthreads();
    float var = red[33] * (1.f / DM);
    float inv = rsqrtf(var + EPSLN);
    float y = g[t] * xc * inv + beta[t];

    const int n = row / LQ, r = row % LQ;
    const size_t P1 = (size_t)NB * L_SP * DM;
    const size_t P2 = (size_t)NB * 75 * N_VT * DM;
    size_t oidx;
    if (r < L_SP) oidx = ((size_t)n * L_SP + r) * DM + t;
    else          oidx = P1 + P2 + ((size_t)n * N_VT + (r - L_SP)) * DM + t;
    out[oidx] = y;
}

// ---------------- all_vt passthrough copy ----------------
__global__ void copy_vt_kernel(const float* __restrict__ all_vt, float* __restrict__ out)
{
    const size_t P1 = (size_t)NB * L_SP * DM;
    const size_t P2 = (size_t)NB * 75 * N_VT * DM;
    size_t idx = (size_t)blockIdx.x * blockDim.x + threadIdx.x;
    if (idx < P2) out[P1 + idx] = all_vt[idx];
}

// ---------------- launch ----------------
extern "C" void kernel_launch(void* const* d_in, const int* in_sizes, int n_in,
                              void* d_out, int out_size)
{
    const float* src     = (const float*)d_in[0];
    const float* pos     = (const float*)d_in[1];
    const float* refpts  = (const float*)d_in[2];
    const float* all_vt  = (const float*)d_in[6];
    const float* sel_vt  = (const float*)d_in[7];
    const float* W_value = (const float*)d_in[8];
    const float* b_value = (const float*)d_in[9];
    const float* W_off   = (const float*)d_in[10];
    const float* b_off   = (const float*)d_in[11];
    const float* W_attn  = (const float*)d_in[12];
    const float* b_attn  = (const float*)d_in[13];
    const float* W_out   = (const float*)d_in[14];
    const float* b_out   = (const float*)d_in[15];
    const float* g1      = (const float*)d_in[16];
    const float* beta1   = (const float*)d_in[17];
    const float* W1      = (const float*)d_in[18];
    const float* bf1     = (const float*)d_in[19];
    const float* W2      = (const float*)d_in[20];
    const float* bf2     = (const float*)d_in[21];
    const float* g2      = (const float*)d_in[22];
    const float* beta2   = (const float*)d_in[23];
    float* out = (float*)d_out;

    float* p_v;    cudaGetSymbolAddress((void**)&p_v,    g_v);
    float* p_off;  cudaGetSymbolAddress((void**)&p_off,  g_off);
    float* p_attn; cudaGetSymbolAddress((void**)&p_attn, g_attn);
    float* p_tmp;  cudaGetSymbolAddress((void**)&p_tmp,  g_tmp);
    float* p_x;    cudaGetSymbolAddress((void**)&p_x,    g_x);
    __half *p_valh, *p_qh, *p_vh, *p_sh, *p_xh, *p_h1h, *p_wh;
    cudaGetSymbolAddress((void**)&p_valh, g_valh);
    cudaGetSymbolAddress((void**)&p_qh,  g_qh);
    cudaGetSymbolAddress((void**)&p_vh,  g_vh);
    cudaGetSymbolAddress((void**)&p_sh,  g_sh);
    cudaGetSymbolAddress((void**)&p_xh,  g_xh);
    cudaGetSymbolAddress((void**)&p_h1h, g_h1h);
    cudaGetSymbolAddress((void**)&p_wh,  g_wh);

    static int smem_set = 0;
    if (!smem_set) {
        cudaFuncSetAttribute(mma_gemm_kernel, cudaFuncAttributeMaxDynamicSharedMemorySize, GSM_TOTAL);
        smem_set = 1;
    }

    const int M = ROWS;
    const int MT = (M + 127) / 128;   // 171

    // 1. build q, v
    {
        size_t total = (size_t)ROWS * DM;
        build_qv_kernel<<<(unsigned)((total + 255) / 256), 256>>>(src, pos, sel_vt);
    }
    // 2. weight conversion
    conv_all_kernel<<<(WTOT + 255) / 256, 256>>>(W_value, W_off, W_attn, W_out, W1, W2);

    // 3. value projection -> fp16 (sampling source)
    mma_gemm_kernel<<<dim3(4, MT), 256, GSM_TOTAL>>>(p_vh, p_wh + WOFF_V,
        b_value, nullptr, nullptr, nullptr, p_valh, M, DM, DM, 0);
    // 4. fused offsets+attn: B = [Wo; Wa], N=384; cols<256 -> g_off, cols>=256 -> g_attn (raw logits)
    mma_gemm_kernel<<<dim3(6, MT), 256, GSM_TOTAL>>>(p_qh, p_wh + WOFF_O,
        b_off, b_attn, p_off, p_attn, nullptr, M, DM, DM, 0);
    // 5. deformable sampling (softmax fused) -> fp16
    sample_kernel<<<ROWS, 256>>>(refpts);
    // 6. output projection -> g_tmp
    mma_gemm_kernel<<<dim3(4, MT), 256, GSM_TOTAL>>>(p_sh, p_wh + WOFF_OUT,
        b_out, nullptr, p_tmp, nullptr, nullptr, M, DM, DM, 0);
    // 7. x = LN(v + src2) (+ fp16)
    resid_ln_kernel<<<ROWS, 256>>>(p_v, p_tmp, g1, beta1, p_x, p_xh);
    // 8. h1 = relu(x @ W1^T + bf1) -> fp16 (N=1024)
    mma_gemm_kernel<<<dim3(16, MT), 256, GSM_TOTAL>>>(p_xh, p_wh + WOFF_1,
        bf1, nullptr, nullptr, nullptr, p_h1h, M, DF, DM, 1);
    // 9. h = h1 @ W2^T + bf2 -> g_tmp (K=1024)
    mma_gemm_kernel<<<dim3(4, MT), 256, GSM_TOTAL>>>(p_h1h, p_wh + WOFF_2,
        bf2, nullptr, p_tmp, nullptr, nullptr, M, DM, DF, 0);
    // 10. x = LN(x + h) -> directly into d_out (mapped)
    resid_ln_out_kernel<<<ROWS, 256>>>(p_x, p_tmp, g2, beta2, out);
    // 11. all_vt passthrough
    {
        size_t total = (size_t)NB * 75 * N_VT * DM;
        copy_vt_kernel<<<(unsigned)((total + 255) / 256), 256>>>(all_vt, out);
    }
}